// round 7
// baseline (speedup 1.0000x reference)
#include <cuda_runtime.h>
#include <cstdint>

#define NCC   100000   // n_coarse
#define NFF   400000   // n_fine
#define CDIM  64
#define EPMAX 1200000
#define ECMAX 1600000
#define EUMAX 1200000

typedef unsigned long long u64;

// ---------------- scratch ----------------
__device__ float g_xc[(size_t)NCC * CDIM];
__device__ float g_t [(size_t)NCC * CDIM];
__device__ float g_h [(size_t)NCC * CDIM];

// CSR build scratch
__device__ int  g_pool_cnt[NCC + 4];
__device__ int  g_pool_off[NCC + 4];
__device__ int  g_pool_cur[NCC];
__device__ int2 g_pool_edges[EPMAX];

__device__ int  g_conv_cnt[NCC + 4];
__device__ int  g_conv_off[NCC + 4];
__device__ int  g_conv_cur[NCC];
__device__ int2 g_conv_edges[ECMAX];

__device__ int  g_unp_cnt[NFF + 4];
__device__ int  g_unp_off[NFF + 4];
__device__ int  g_unp_cur[NFF];
__device__ int2 g_unp_edges[EUMAX];

__device__ int  g_bsum[3 * 512];

// ---------------- helpers ----------------
__device__ __forceinline__ u64 pack2(float x) {
    u64 r;
    asm("mov.b64 %0, {%1, %1};" : "=l"(r) : "f"(x));
    return r;
}
__device__ __forceinline__ void fma2(u64& d, u64 a, u64 b) {
    asm("fma.rn.f32x2 %0, %1, %2, %0;" : "+l"(d) : "l"(a), "l"(b));
}

// ---------------- small utility kernels (int4-vectorized) ----------------
__global__ void zero_int(int* __restrict__ p, int n) {
    int i = (blockIdx.x * blockDim.x + threadIdx.x) * 4;
    if (i + 3 < n) {
        *reinterpret_cast<int4*>(p + i) = make_int4(0, 0, 0, 0);
    } else {
        for (int j = i; j < n && j < i + 4; j++) p[j] = 0;
    }
}

__global__ void hist_kernel(const int* __restrict__ dst, int* __restrict__ cnt, int E) {
    int i = (blockIdx.x * blockDim.x + threadIdx.x) * 4;
    if (i + 3 < E) {
        int4 d = *reinterpret_cast<const int4*>(dst + i);
        atomicAdd(&cnt[d.x], 1);
        atomicAdd(&cnt[d.y], 1);
        atomicAdd(&cnt[d.z], 1);
        atomicAdd(&cnt[d.w], 1);
    } else {
        for (int j = i; j < E && j < i + 4; j++) atomicAdd(&cnt[dst[j]], 1);
    }
}

// ---- scan level 1: per-block (1024 elems) reduction via shfl ----
__global__ void __launch_bounds__(256) reduce_blk(
    const int* __restrict__ cnt, int* __restrict__ bsum, int n)
{
    __shared__ int ws[8];
    int tid = threadIdx.x;
    int base = blockIdx.x * 1024 + tid * 4;
    int s = 0;
    if (base + 3 < n) {
        int4 v = *reinterpret_cast<const int4*>(cnt + base);
        s = v.x + v.y + v.z + v.w;
    } else {
        for (int j = base; j < n && j < base + 4; j++) s += cnt[j];
    }
#pragma unroll
    for (int o = 16; o; o >>= 1) s += __shfl_down_sync(0xffffffffu, s, o);
    if ((tid & 31) == 0) ws[tid >> 5] = s;
    __syncthreads();
    if (tid < 8) {
        int t = ws[tid];
#pragma unroll
        for (int o = 4; o; o >>= 1) t += __shfl_down_sync(0xffu, t, o);
        if (tid == 0) bsum[blockIdx.x] = t;
    }
}

// ---- scan level 2: exclusive scan of nb (<=512) partials ----
__global__ void __launch_bounds__(512) scan_partials(int* __restrict__ bsum, int nb) {
    __shared__ int ws[16];
    int tid = threadIdx.x, lane = tid & 31, wid = tid >> 5;
    int v = (tid < nb) ? bsum[tid] : 0;
    int p = v;
#pragma unroll
    for (int o = 1; o < 32; o <<= 1) {
        int t = __shfl_up_sync(0xffffffffu, p, o);
        if (lane >= o) p += t;
    }
    if (lane == 31) ws[wid] = p;
    __syncthreads();
    if (tid < 16) {
        int t = ws[tid];
        int q = t;
#pragma unroll
        for (int o = 1; o < 16; o <<= 1) {
            int u = __shfl_up_sync(0xffffu, q, o);
            if (tid >= o) q += u;
        }
        ws[tid] = q - t;
    }
    __syncthreads();
    if (tid < nb) bsum[tid] = p - v + ws[wid];
}

// ---- scan level 3: in-block exclusive scan + block offset ----
__global__ void __launch_bounds__(256) scan_final(
    const int* __restrict__ cnt, const int* __restrict__ bsum,
    int* __restrict__ off, int* __restrict__ cursor, int n)
{
    __shared__ int ws[8];
    int tid = threadIdx.x, lane = tid & 31, wid = tid >> 5;
    int base = blockIdx.x * 1024 + tid * 4;
    int v0 = 0, v1 = 0, v2 = 0, v3 = 0;
    if (base + 3 < n) {
        int4 v = *reinterpret_cast<const int4*>(cnt + base);
        v0 = v.x; v1 = v.y; v2 = v.z; v3 = v.w;
    } else {
        if (base + 0 < n) v0 = cnt[base + 0];
        if (base + 1 < n) v1 = cnt[base + 1];
        if (base + 2 < n) v2 = cnt[base + 2];
        if (base + 3 < n) v3 = cnt[base + 3];
    }
    int s = v0 + v1 + v2 + v3;
    int p = s;
#pragma unroll
    for (int o = 1; o < 32; o <<= 1) {
        int t = __shfl_up_sync(0xffffffffu, p, o);
        if (lane >= o) p += t;
    }
    if (lane == 31) ws[wid] = p;
    __syncthreads();
    if (tid < 8) {
        int t = ws[tid];
        int q = t;
#pragma unroll
        for (int o = 1; o < 8; o <<= 1) {
            int u = __shfl_up_sync(0xffu, q, o);
            if (tid >= o) q += u;
        }
        ws[tid] = q - t;
    }
    __syncthreads();
    int excl = __ldg(bsum + blockIdx.x) + ws[wid] + (p - s);

    int o0 = excl, o1 = excl + v0, o2 = o1 + v1, o3 = o2 + v2;
    if (base + 3 < n) {
        *reinterpret_cast<int4*>(off + base) = make_int4(o0, o1, o2, o3);
    } else {
        if (base + 0 < n) off[base + 0] = o0;
        if (base + 1 < n) off[base + 1] = o1;
        if (base + 2 < n) off[base + 2] = o2;
        if (base + 3 < n) off[base + 3] = o3;
    }
    if (base + 0 < n - 1) cursor[base + 0] = o0;
    if (base + 1 < n - 1) cursor[base + 1] = o1;
    if (base + 2 < n - 1) cursor[base + 2] = o2;
    if (base + 3 < n - 1) cursor[base + 3] = o3;
}

__global__ void permute_kernel(const int* __restrict__ src, const int* __restrict__ dst,
                               const float* __restrict__ attr, int* __restrict__ cursor,
                               int2* __restrict__ edges, int E) {
    int i = (blockIdx.x * blockDim.x + threadIdx.x) * 4;
    if (i + 3 < E) {
        int4   sv = *reinterpret_cast<const int4*>(src + i);
        int4   dv = *reinterpret_cast<const int4*>(dst + i);
        float4 av = *reinterpret_cast<const float4*>(attr + i);
        int p0 = atomicAdd(&cursor[dv.x], 1);
        int p1 = atomicAdd(&cursor[dv.y], 1);
        int p2 = atomicAdd(&cursor[dv.z], 1);
        int p3 = atomicAdd(&cursor[dv.w], 1);
        edges[p0] = make_int2(sv.x, __float_as_int(av.x));
        edges[p1] = make_int2(sv.y, __float_as_int(av.y));
        edges[p2] = make_int2(sv.z, __float_as_int(av.z));
        edges[p3] = make_int2(sv.w, __float_as_int(av.w));
    } else {
        for (int j = i; j < E && j < i + 4; j++) {
            int p = atomicAdd(&cursor[dst[j]], 1);
            edges[p] = make_int2(src[j], __float_as_int(attr[j]));
        }
    }
}

// ---------------- CSR gather: 8 threads/node, 2x float4 per thread (R5 form) ----------------
template <bool INIT_FROM_OUT>
__global__ void __launch_bounds__(256) gather_kernel(
    const float* __restrict__ feat,
    const int2*  __restrict__ edges,
    const int*   __restrict__ off,
    float*       __restrict__ outp,
    int n)
{
    int idx = blockIdx.x * blockDim.x + threadIdx.x;
    int node = idx >> 3;
    if (node >= n) return;
    int q = (idx & 7) << 3;

    int e0 = __ldg(off + node);
    int e1 = __ldg(off + node + 1);

    float* orow = outp + (size_t)node * CDIM + q;
    float4 acc0, acc1;
    if (INIT_FROM_OUT) {
        acc0 = *reinterpret_cast<const float4*>(orow);
        acc1 = *reinterpret_cast<const float4*>(orow + 4);
    } else {
        acc0 = make_float4(0.f, 0.f, 0.f, 0.f);
        acc1 = acc0;
    }

#pragma unroll 2
    for (int e = e0; e < e1; e++) {
        int2 ed = __ldg(edges + e);
        float w = __int_as_float(ed.y);
        const float4* p = reinterpret_cast<const float4*>(feat + (size_t)ed.x * CDIM + q);
        float4 v0 = __ldg(p);
        float4 v1 = __ldg(p + 1);
        acc0.x = fmaf(w, v0.x, acc0.x);
        acc0.y = fmaf(w, v0.y, acc0.y);
        acc0.z = fmaf(w, v0.z, acc0.z);
        acc0.w = fmaf(w, v0.w, acc0.w);
        acc1.x = fmaf(w, v1.x, acc1.x);
        acc1.y = fmaf(w, v1.y, acc1.y);
        acc1.z = fmaf(w, v1.z, acc1.z);
        acc1.w = fmaf(w, v1.w, acc1.w);
    }
    *reinterpret_cast<float4*>(orow)     = acc0;
    *reinterpret_cast<float4*>(orow + 4) = acc1;
}

// ---------------- fused dual GEMM: 8-row x 4-col thread tiles ----------------
// Block: 256 threads, tile = 128 rows x 64 cols.
// Thread t: cg = t & 15 (cols cg*4..+3), rg = t >> 4 (rows rg*8..+7).
// Per k: weight smem traffic = 2 matrices x 1 LDS.128; A restaged 8x LDS.128 / k4.
// Crossbar ~64B/thread/k vs 32 FFMA2 -> FFMA2-bound.
#define ROWS_PER_BLK 128
#define SA_STRIDE    68

__global__ void __launch_bounds__(256, 2) dual_gemm(
    const float* __restrict__ A,
    const float* __restrict__ Wn,
    const float* __restrict__ Wr,
    const float* __restrict__ bias,
    float* __restrict__ T,
    float* __restrict__ H,
    int N)
{
    __shared__ float sWn[CDIM * CDIM];
    __shared__ float sWr[CDIM * CDIM];
    __shared__ float sA[ROWS_PER_BLK * SA_STRIDE];

    const int t = threadIdx.x;

    {
        const float4* Wn4 = reinterpret_cast<const float4*>(Wn);
        const float4* Wr4 = reinterpret_cast<const float4*>(Wr);
        float4* sWn4 = reinterpret_cast<float4*>(sWn);
        float4* sWr4 = reinterpret_cast<float4*>(sWr);
#pragma unroll
        for (int i = 0; i < 4; i++) {
            sWn4[t + 256 * i] = Wn4[t + 256 * i];
            sWr4[t + 256 * i] = Wr4[t + 256 * i];
        }
    }

    const int rowBase = blockIdx.x * ROWS_PER_BLK;
#pragma unroll
    for (int i = 0; i < 8; i++) {
        int idx = t + 256 * i;
        int row = idx >> 4;
        int kc  = (idx & 15) * 4;
        float4 a;
        if (rowBase + row < N)
            a = *reinterpret_cast<const float4*>(A + (size_t)(rowBase + row) * CDIM + kc);
        else
            a = make_float4(0.f, 0.f, 0.f, 0.f);
        *reinterpret_cast<float4*>(sA + row * SA_STRIDE + kc) = a;
    }
    __syncthreads();

    const int cg = t & 15;
    const int rg = t >> 4;
    const int c0 = cg * 4;
    const int r0 = rg * 8;

    // accumulators: 8 rows x 4 cols x 2 outputs = 64 fp32 = 32 u64
    u64 accT[8][2], accR[8][2];
    {
        ulonglong2 bv = *reinterpret_cast<const ulonglong2*>(bias + c0);
#pragma unroll
        for (int r = 0; r < 8; r++) {
            accT[r][0] = 0ull; accT[r][1] = 0ull;
            accR[r][0] = bv.x; accR[r][1] = bv.y;
        }
    }

#pragma unroll 2
    for (int k4 = 0; k4 < 16; k4++) {
        // stage A: 8 rows x 4 k-values, one LDS.128 per row
        float4 a[8];
#pragma unroll
        for (int r = 0; r < 8; r++)
            a[r] = *reinterpret_cast<const float4*>(sA + (r0 + r) * SA_STRIDE + k4 * 4);
#pragma unroll
        for (int j = 0; j < 4; j++) {
            const int k = k4 * 4 + j;
            ulonglong2 nw = *reinterpret_cast<const ulonglong2*>(sWn + k * CDIM + c0);
            ulonglong2 qw = *reinterpret_cast<const ulonglong2*>(sWr + k * CDIM + c0);
            u64 n0 = nw.x, n1 = nw.y;
            u64 q0 = qw.x, q1 = qw.y;
#pragma unroll
            for (int r = 0; r < 8; r++) {
                float av = (j == 0) ? a[r].x : (j == 1) ? a[r].y : (j == 2) ? a[r].z : a[r].w;
                u64 ap = pack2(av);
                fma2(accT[r][0], ap, n0);
                fma2(accT[r][1], ap, n1);
                fma2(accR[r][0], ap, q0);
                fma2(accR[r][1], ap, q1);
            }
        }
    }

#pragma unroll
    for (int r = 0; r < 8; r++) {
        const int grow = rowBase + r0 + r;
        if (grow < N) {
            ulonglong2 tv, hv;
            tv.x = accT[r][0]; tv.y = accT[r][1];
            hv.x = accR[r][0]; hv.y = accR[r][1];
            *reinterpret_cast<ulonglong2*>(T + (size_t)grow * CDIM + c0) = tv;
            *reinterpret_cast<ulonglong2*>(H + (size_t)grow * CDIM + c0) = hv;
        }
    }
}

// ---------------- host-side CSR build helper ----------------
static void build_csr(const int* src, const int* dst, const float* attr, int E,
                      int* cnt, int* off, int* cur, int2* edges, int* bsum, int nNodes,
                      cudaStream_t s)
{
    const int n1 = nNodes + 1;
    const int nb = (n1 + 1023) / 1024;
    zero_int<<<(n1 + 1023) / 1024, 256, 0, s>>>(cnt, n1);
    hist_kernel<<<(E + 1023) / 1024, 256, 0, s>>>(dst, cnt, E);
    reduce_blk<<<nb, 256, 0, s>>>(cnt, bsum, n1);
    scan_partials<<<1, 512, 0, s>>>(bsum, nb);
    scan_final<<<nb, 256, 0, s>>>(cnt, bsum, off, cur, n1);
    permute_kernel<<<(E + 1023) / 1024, 256, 0, s>>>(src, dst, attr, cur, edges, E);
}

// ---------------- launch ----------------
extern "C" void kernel_launch(void* const* d_in, const int* in_sizes, int n_in,
                              void* d_out, int out_size)
{
    const float* x    = (const float*)d_in[0];
    const float* W1r  = (const float*)d_in[1];
    const float* W1n  = (const float*)d_in[2];
    const float* b1   = (const float*)d_in[3];
    const float* W2r  = (const float*)d_in[4];
    const float* W2n  = (const float*)d_in[5];
    const float* b2   = (const float*)d_in[6];
    const int*   psrc = (const int*)d_in[7];
    const int*   pdst = (const int*)d_in[8];
    const float* patt = (const float*)d_in[9];
    const int*   csrc = (const int*)d_in[10];
    const int*   cdst = (const int*)d_in[11];
    const float* catt = (const float*)d_in[12];
    const int*   usrc = (const int*)d_in[13];
    const int*   udst = (const int*)d_in[14];
    const float* uatt = (const float*)d_in[15];

    const int Ep = in_sizes[7];
    const int Ec = in_sizes[10];
    const int Eu = in_sizes[13];

    float* out = (float*)d_out;

    float *xc, *tb, *hb;
    cudaGetSymbolAddress((void**)&xc, g_xc);
    cudaGetSymbolAddress((void**)&tb, g_t);
    cudaGetSymbolAddress((void**)&hb, g_h);

    int *pcnt, *poff, *pcur, *ccnt, *coff, *ccur, *ucnt, *uoff, *ucur, *bsum;
    int2 *pedg, *cedg, *uedg;
    cudaGetSymbolAddress((void**)&pcnt, g_pool_cnt);
    cudaGetSymbolAddress((void**)&poff, g_pool_off);
    cudaGetSymbolAddress((void**)&pcur, g_pool_cur);
    cudaGetSymbolAddress((void**)&pedg, g_pool_edges);
    cudaGetSymbolAddress((void**)&ccnt, g_conv_cnt);
    cudaGetSymbolAddress((void**)&coff, g_conv_off);
    cudaGetSymbolAddress((void**)&ccur, g_conv_cur);
    cudaGetSymbolAddress((void**)&cedg, g_conv_edges);
    cudaGetSymbolAddress((void**)&ucnt, g_unp_cnt);
    cudaGetSymbolAddress((void**)&uoff, g_unp_off);
    cudaGetSymbolAddress((void**)&ucur, g_unp_cur);
    cudaGetSymbolAddress((void**)&uedg, g_unp_edges);
    cudaGetSymbolAddress((void**)&bsum, g_bsum);

    static cudaStream_t sB = nullptr, sC = nullptr;
    static cudaEvent_t ev0 = nullptr, evB = nullptr, evC = nullptr;
    if (sB == nullptr) {
        cudaStreamCreateWithFlags(&sB, cudaStreamNonBlocking);
        cudaStreamCreateWithFlags(&sC, cudaStreamNonBlocking);
        cudaEventCreateWithFlags(&ev0, cudaEventDisableTiming);
        cudaEventCreateWithFlags(&evB, cudaEventDisableTiming);
        cudaEventCreateWithFlags(&evC, cudaEventDisableTiming);
    }

    // fork: conv CSR on sB, unpool CSR on sC
    cudaEventRecord(ev0, 0);
    cudaStreamWaitEvent(sB, ev0, 0);
    cudaStreamWaitEvent(sC, ev0, 0);
    build_csr(csrc, cdst, catt, Ec, ccnt, coff, ccur, cedg, bsum + 512,  NCC, sB);
    cudaEventRecord(evB, sB);
    build_csr(usrc, udst, uatt, Eu, ucnt, uoff, ucur, uedg, bsum + 1024, NFF, sC);
    cudaEventRecord(evC, sC);

    // critical path
    build_csr(psrc, pdst, patt, Ep, pcnt, poff, pcur, pedg, bsum, NCC, 0);

    const int gthreadsC = NCC * 8;
    const int gthreadsF = NFF * 8;

    gather_kernel<false><<<(gthreadsC + 255) / 256, 256>>>(x, pedg, poff, xc, NCC);

    dual_gemm<<<(NCC + ROWS_PER_BLK - 1) / ROWS_PER_BLK, 256>>>(xc, W1n, W1r, b1, tb, hb, NCC);
    cudaStreamWaitEvent(0, evB, 0);
    gather_kernel<true><<<(gthreadsC + 255) / 256, 256>>>(tb, cedg, coff, hb, NCC);

    dual_gemm<<<(NCC + ROWS_PER_BLK - 1) / ROWS_PER_BLK, 256>>>(hb, W2n, W2r, b2, tb, xc, NCC);
    gather_kernel<true><<<(gthreadsC + 255) / 256, 256>>>(tb, cedg, coff, xc, NCC);

    cudaStreamWaitEvent(0, evC, 0);
    gather_kernel<false><<<(gthreadsF + 255) / 256, 256>>>(xc, uedg, uoff, out, NFF);
}

// round 8
// speedup vs baseline: 1.3606x; 1.3606x over previous
#include <cuda_runtime.h>
#include <cuda_fp16.h>
#include <cstdint>

#define NCC   100000   // n_coarse
#define NFF   400000   // n_fine
#define CDIM  64
#define EPMAX 1200000
#define ECMAX 1600000
#define EUMAX 1200000

typedef unsigned long long u64;

// ---------------- scratch ----------------
__device__ float  g_xc[(size_t)NCC * CDIM];
__device__ __half g_t [(size_t)NCC * CDIM];   // fp16 neighbor-transformed features
__device__ float  g_h [(size_t)NCC * CDIM];

// CSR build scratch
__device__ int  g_pool_cnt[NCC + 4];
__device__ int  g_pool_off[NCC + 4];
__device__ int  g_pool_cur[NCC];
__device__ int2 g_pool_edges[EPMAX];

__device__ int  g_conv_cnt[NCC + 4];
__device__ int  g_conv_off[NCC + 4];
__device__ int  g_conv_cur[NCC];
__device__ int2 g_conv_edges[ECMAX];

__device__ int  g_unp_cnt[NFF + 4];
__device__ int  g_unp_off[NFF + 4];
__device__ int  g_unp_cur[NFF];
__device__ int2 g_unp_edges[EUMAX];

__device__ int  g_bsum[3 * 512];

// ---------------- helpers ----------------
__device__ __forceinline__ u64 pack2(float x) {
    u64 r;
    asm("mov.b64 %0, {%1, %1};" : "=l"(r) : "f"(x));
    return r;
}
__device__ __forceinline__ void fma2(u64& d, u64 a, u64 b) {
    asm("fma.rn.f32x2 %0, %1, %2, %0;" : "+l"(d) : "l"(a), "l"(b));
}
__device__ __forceinline__ uint32_t pack_h2(u64 v) {
    float lo = __int_as_float((int)(v & 0xffffffffull));
    float hi = __int_as_float((int)(v >> 32));
    __half2 h = __floats2half2_rn(lo, hi);
    return *reinterpret_cast<uint32_t*>(&h);
}

// ---------------- small utility kernels (int4-vectorized) ----------------
__global__ void zero_int(int* __restrict__ p, int n) {
    int i = (blockIdx.x * blockDim.x + threadIdx.x) * 4;
    if (i + 3 < n) {
        *reinterpret_cast<int4*>(p + i) = make_int4(0, 0, 0, 0);
    } else {
        for (int j = i; j < n && j < i + 4; j++) p[j] = 0;
    }
}

__global__ void hist_kernel(const int* __restrict__ dst, int* __restrict__ cnt, int E) {
    int i = (blockIdx.x * blockDim.x + threadIdx.x) * 4;
    if (i + 3 < E) {
        int4 d = *reinterpret_cast<const int4*>(dst + i);
        atomicAdd(&cnt[d.x], 1);
        atomicAdd(&cnt[d.y], 1);
        atomicAdd(&cnt[d.z], 1);
        atomicAdd(&cnt[d.w], 1);
    } else {
        for (int j = i; j < E && j < i + 4; j++) atomicAdd(&cnt[dst[j]], 1);
    }
}

__global__ void __launch_bounds__(256) reduce_blk(
    const int* __restrict__ cnt, int* __restrict__ bsum, int n)
{
    __shared__ int ws[8];
    int tid = threadIdx.x;
    int base = blockIdx.x * 1024 + tid * 4;
    int s = 0;
    if (base + 3 < n) {
        int4 v = *reinterpret_cast<const int4*>(cnt + base);
        s = v.x + v.y + v.z + v.w;
    } else {
        for (int j = base; j < n && j < base + 4; j++) s += cnt[j];
    }
#pragma unroll
    for (int o = 16; o; o >>= 1) s += __shfl_down_sync(0xffffffffu, s, o);
    if ((tid & 31) == 0) ws[tid >> 5] = s;
    __syncthreads();
    if (tid < 8) {
        int t = ws[tid];
#pragma unroll
        for (int o = 4; o; o >>= 1) t += __shfl_down_sync(0xffu, t, o);
        if (tid == 0) bsum[blockIdx.x] = t;
    }
}

__global__ void __launch_bounds__(512) scan_partials(int* __restrict__ bsum, int nb) {
    __shared__ int ws[16];
    int tid = threadIdx.x, lane = tid & 31, wid = tid >> 5;
    int v = (tid < nb) ? bsum[tid] : 0;
    int p = v;
#pragma unroll
    for (int o = 1; o < 32; o <<= 1) {
        int t = __shfl_up_sync(0xffffffffu, p, o);
        if (lane >= o) p += t;
    }
    if (lane == 31) ws[wid] = p;
    __syncthreads();
    if (tid < 16) {
        int t = ws[tid];
        int q = t;
#pragma unroll
        for (int o = 1; o < 16; o <<= 1) {
            int u = __shfl_up_sync(0xffffu, q, o);
            if (tid >= o) q += u;
        }
        ws[tid] = q - t;
    }
    __syncthreads();
    if (tid < nb) bsum[tid] = p - v + ws[wid];
}

__global__ void __launch_bounds__(256) scan_final(
    const int* __restrict__ cnt, const int* __restrict__ bsum,
    int* __restrict__ off, int* __restrict__ cursor, int n)
{
    __shared__ int ws[8];
    int tid = threadIdx.x, lane = tid & 31, wid = tid >> 5;
    int base = blockIdx.x * 1024 + tid * 4;
    int v0 = 0, v1 = 0, v2 = 0, v3 = 0;
    if (base + 3 < n) {
        int4 v = *reinterpret_cast<const int4*>(cnt + base);
        v0 = v.x; v1 = v.y; v2 = v.z; v3 = v.w;
    } else {
        if (base + 0 < n) v0 = cnt[base + 0];
        if (base + 1 < n) v1 = cnt[base + 1];
        if (base + 2 < n) v2 = cnt[base + 2];
        if (base + 3 < n) v3 = cnt[base + 3];
    }
    int s = v0 + v1 + v2 + v3;
    int p = s;
#pragma unroll
    for (int o = 1; o < 32; o <<= 1) {
        int t = __shfl_up_sync(0xffffffffu, p, o);
        if (lane >= o) p += t;
    }
    if (lane == 31) ws[wid] = p;
    __syncthreads();
    if (tid < 8) {
        int t = ws[tid];
        int q = t;
#pragma unroll
        for (int o = 1; o < 8; o <<= 1) {
            int u = __shfl_up_sync(0xffu, q, o);
            if (tid >= o) q += u;
        }
        ws[tid] = q - t;
    }
    __syncthreads();
    int excl = __ldg(bsum + blockIdx.x) + ws[wid] + (p - s);

    int o0 = excl, o1 = excl + v0, o2 = o1 + v1, o3 = o2 + v2;
    if (base + 3 < n) {
        *reinterpret_cast<int4*>(off + base) = make_int4(o0, o1, o2, o3);
    } else {
        if (base + 0 < n) off[base + 0] = o0;
        if (base + 1 < n) off[base + 1] = o1;
        if (base + 2 < n) off[base + 2] = o2;
        if (base + 3 < n) off[base + 3] = o3;
    }
    if (base + 0 < n - 1) cursor[base + 0] = o0;
    if (base + 1 < n - 1) cursor[base + 1] = o1;
    if (base + 2 < n - 1) cursor[base + 2] = o2;
    if (base + 3 < n - 1) cursor[base + 3] = o3;
}

__global__ void permute_kernel(const int* __restrict__ src, const int* __restrict__ dst,
                               const float* __restrict__ attr, int* __restrict__ cursor,
                               int2* __restrict__ edges, int E) {
    int i = (blockIdx.x * blockDim.x + threadIdx.x) * 4;
    if (i + 3 < E) {
        int4   sv = *reinterpret_cast<const int4*>(src + i);
        int4   dv = *reinterpret_cast<const int4*>(dst + i);
        float4 av = *reinterpret_cast<const float4*>(attr + i);
        int p0 = atomicAdd(&cursor[dv.x], 1);
        int p1 = atomicAdd(&cursor[dv.y], 1);
        int p2 = atomicAdd(&cursor[dv.z], 1);
        int p3 = atomicAdd(&cursor[dv.w], 1);
        edges[p0] = make_int2(sv.x, __float_as_int(av.x));
        edges[p1] = make_int2(sv.y, __float_as_int(av.y));
        edges[p2] = make_int2(sv.z, __float_as_int(av.z));
        edges[p3] = make_int2(sv.w, __float_as_int(av.w));
    } else {
        for (int j = i; j < E && j < i + 4; j++) {
            int p = atomicAdd(&cursor[dst[j]], 1);
            edges[p] = make_int2(src[j], __float_as_int(attr[j]));
        }
    }
}

// ---------------- CSR gather (fp32 features): 8 threads/node, 2x float4 ----------------
template <bool INIT_FROM_OUT>
__global__ void __launch_bounds__(256) gather_kernel(
    const float* __restrict__ feat,
    const int2*  __restrict__ edges,
    const int*   __restrict__ off,
    float*       __restrict__ outp,
    int n)
{
    int idx = blockIdx.x * blockDim.x + threadIdx.x;
    int node = idx >> 3;
    if (node >= n) return;
    int q = (idx & 7) << 3;

    int e0 = __ldg(off + node);
    int e1 = __ldg(off + node + 1);

    float* orow = outp + (size_t)node * CDIM + q;
    float4 acc0, acc1;
    if (INIT_FROM_OUT) {
        acc0 = *reinterpret_cast<const float4*>(orow);
        acc1 = *reinterpret_cast<const float4*>(orow + 4);
    } else {
        acc0 = make_float4(0.f, 0.f, 0.f, 0.f);
        acc1 = acc0;
    }

#pragma unroll 2
    for (int e = e0; e < e1; e++) {
        int2 ed = __ldg(edges + e);
        float w = __int_as_float(ed.y);
        const float4* p = reinterpret_cast<const float4*>(feat + (size_t)ed.x * CDIM + q);
        float4 v0 = __ldg(p);
        float4 v1 = __ldg(p + 1);
        acc0.x = fmaf(w, v0.x, acc0.x);
        acc0.y = fmaf(w, v0.y, acc0.y);
        acc0.z = fmaf(w, v0.z, acc0.z);
        acc0.w = fmaf(w, v0.w, acc0.w);
        acc1.x = fmaf(w, v1.x, acc1.x);
        acc1.y = fmaf(w, v1.y, acc1.y);
        acc1.z = fmaf(w, v1.z, acc1.z);
        acc1.w = fmaf(w, v1.w, acc1.w);
    }
    *reinterpret_cast<float4*>(orow)     = acc0;
    *reinterpret_cast<float4*>(orow + 4) = acc1;
}

// ---------------- CSR gather (fp16 features): 8 threads/node, 1x uint4 ----------------
// Half the L2 read traffic of the fp32 gather; fp32 accumulation.
__global__ void __launch_bounds__(256) gather_half(
    const __half* __restrict__ feat,
    const int2*   __restrict__ edges,
    const int*    __restrict__ off,
    float*        __restrict__ outp,
    int n)
{
    int idx = blockIdx.x * blockDim.x + threadIdx.x;
    int node = idx >> 3;
    if (node >= n) return;
    int q = (idx & 7) << 3;   // half index within row

    int e0 = __ldg(off + node);
    int e1 = __ldg(off + node + 1);

    float* orow = outp + (size_t)node * CDIM + q;
    float4 acc0 = *reinterpret_cast<const float4*>(orow);
    float4 acc1 = *reinterpret_cast<const float4*>(orow + 4);

#pragma unroll 2
    for (int e = e0; e < e1; e++) {
        int2 ed = __ldg(edges + e);
        float w = __int_as_float(ed.y);
        uint4 hv = __ldg(reinterpret_cast<const uint4*>(feat + ((size_t)ed.x << 6) + q));
        __half2 h0 = *reinterpret_cast<__half2*>(&hv.x);
        __half2 h1 = *reinterpret_cast<__half2*>(&hv.y);
        __half2 h2 = *reinterpret_cast<__half2*>(&hv.z);
        __half2 h3 = *reinterpret_cast<__half2*>(&hv.w);
        float2 f0 = __half22float2(h0);
        float2 f1 = __half22float2(h1);
        float2 f2 = __half22float2(h2);
        float2 f3 = __half22float2(h3);
        acc0.x = fmaf(w, f0.x, acc0.x);
        acc0.y = fmaf(w, f0.y, acc0.y);
        acc0.z = fmaf(w, f1.x, acc0.z);
        acc0.w = fmaf(w, f1.y, acc0.w);
        acc1.x = fmaf(w, f2.x, acc1.x);
        acc1.y = fmaf(w, f2.y, acc1.y);
        acc1.z = fmaf(w, f3.x, acc1.z);
        acc1.w = fmaf(w, f3.y, acc1.w);
    }
    *reinterpret_cast<float4*>(orow)     = acc0;
    *reinterpret_cast<float4*>(orow + 4) = acc1;
}

// ---------------- fused dual GEMM (R5 config): 4-row x 8-col tiles ----------------
// T output stored as fp16 (consumed only by conv gathers), H as fp32.
#define ROWS_PER_BLK 128
#define SA_STRIDE    68

__global__ void __launch_bounds__(256, 2) dual_gemm(
    const float* __restrict__ A,
    const float* __restrict__ Wn,
    const float* __restrict__ Wr,
    const float* __restrict__ bias,
    __half* __restrict__ T,
    float*  __restrict__ H,
    int N)
{
    __shared__ float sWn[CDIM * CDIM];
    __shared__ float sWr[CDIM * CDIM];
    __shared__ float sA[ROWS_PER_BLK * SA_STRIDE];

    const int t = threadIdx.x;

    {
        const float4* Wn4 = reinterpret_cast<const float4*>(Wn);
        const float4* Wr4 = reinterpret_cast<const float4*>(Wr);
        float4* sWn4 = reinterpret_cast<float4*>(sWn);
        float4* sWr4 = reinterpret_cast<float4*>(sWr);
#pragma unroll
        for (int i = 0; i < 4; i++) {
            sWn4[t + 256 * i] = Wn4[t + 256 * i];
            sWr4[t + 256 * i] = Wr4[t + 256 * i];
        }
    }

    const int rowBase = blockIdx.x * ROWS_PER_BLK;
#pragma unroll
    for (int i = 0; i < 8; i++) {
        int idx = t + 256 * i;
        int row = idx >> 4;
        int kc  = (idx & 15) * 4;
        float4 a;
        if (rowBase + row < N)
            a = *reinterpret_cast<const float4*>(A + (size_t)(rowBase + row) * CDIM + kc);
        else
            a = make_float4(0.f, 0.f, 0.f, 0.f);
        *reinterpret_cast<float4*>(sA + row * SA_STRIDE + kc) = a;
    }
    __syncthreads();

    const int c0 = (t & 7) * 8;
    const int r0 = (t >> 3) * 4;

    u64 accT[4][4], accR[4][4];
    {
        const u64* b2 = reinterpret_cast<const u64*>(bias + c0);
        u64 bv[4];
#pragma unroll
        for (int j = 0; j < 4; j++) bv[j] = b2[j];
#pragma unroll
        for (int r = 0; r < 4; r++)
#pragma unroll
            for (int j = 0; j < 4; j++) { accT[r][j] = 0ull; accR[r][j] = bv[j]; }
    }

    const float4* sA4_0 = reinterpret_cast<const float4*>(sA + (r0 + 0) * SA_STRIDE);
    const float4* sA4_1 = reinterpret_cast<const float4*>(sA + (r0 + 1) * SA_STRIDE);
    const float4* sA4_2 = reinterpret_cast<const float4*>(sA + (r0 + 2) * SA_STRIDE);
    const float4* sA4_3 = reinterpret_cast<const float4*>(sA + (r0 + 3) * SA_STRIDE);

#pragma unroll 4
    for (int k4 = 0; k4 < 16; k4++) {
        float4 a40 = sA4_0[k4];
        float4 a41 = sA4_1[k4];
        float4 a42 = sA4_2[k4];
        float4 a43 = sA4_3[k4];
#pragma unroll
        for (int j = 0; j < 4; j++) {
            const int k = k4 * 4 + j;
            u64 a0 = pack2(j == 0 ? a40.x : j == 1 ? a40.y : j == 2 ? a40.z : a40.w);
            u64 a1 = pack2(j == 0 ? a41.x : j == 1 ? a41.y : j == 2 ? a41.z : a41.w);
            u64 a2 = pack2(j == 0 ? a42.x : j == 1 ? a42.y : j == 2 ? a42.z : a42.w);
            u64 a3 = pack2(j == 0 ? a43.x : j == 1 ? a43.y : j == 2 ? a43.z : a43.w);

            ulonglong2 nA = *reinterpret_cast<const ulonglong2*>(sWn + k * CDIM + c0);
            ulonglong2 nB = *reinterpret_cast<const ulonglong2*>(sWn + k * CDIM + c0 + 4);
            ulonglong2 qA = *reinterpret_cast<const ulonglong2*>(sWr + k * CDIM + c0);
            ulonglong2 qB = *reinterpret_cast<const ulonglong2*>(sWr + k * CDIM + c0 + 4);
            u64 n0 = nA.x, n1 = nA.y, n2 = nB.x, n3 = nB.y;
            u64 q0 = qA.x, q1 = qA.y, q2 = qB.x, q3 = qB.y;

            fma2(accT[0][0], a0, n0); fma2(accT[0][1], a0, n1); fma2(accT[0][2], a0, n2); fma2(accT[0][3], a0, n3);
            fma2(accT[1][0], a1, n0); fma2(accT[1][1], a1, n1); fma2(accT[1][2], a1, n2); fma2(accT[1][3], a1, n3);
            fma2(accT[2][0], a2, n0); fma2(accT[2][1], a2, n1); fma2(accT[2][2], a2, n2); fma2(accT[2][3], a2, n3);
            fma2(accT[3][0], a3, n0); fma2(accT[3][1], a3, n1); fma2(accT[3][2], a3, n2); fma2(accT[3][3], a3, n3);

            fma2(accR[0][0], a0, q0); fma2(accR[0][1], a0, q1); fma2(accR[0][2], a0, q2); fma2(accR[0][3], a0, q3);
            fma2(accR[1][0], a1, q0); fma2(accR[1][1], a1, q1); fma2(accR[1][2], a1, q2); fma2(accR[1][3], a1, q3);
            fma2(accR[2][0], a2, q0); fma2(accR[2][1], a2, q1); fma2(accR[2][2], a2, q2); fma2(accR[2][3], a2, q3);
            fma2(accR[3][0], a3, q0); fma2(accR[3][1], a3, q1); fma2(accR[3][2], a3, q2); fma2(accR[3][3], a3, q3);
        }
    }

#pragma unroll
    for (int r = 0; r < 4; r++) {
        const int grow = rowBase + r0 + r;
        if (grow < N) {
            // T in fp16: 8 halves = 16B
            uint4 tv;
            tv.x = pack_h2(accT[r][0]);
            tv.y = pack_h2(accT[r][1]);
            tv.z = pack_h2(accT[r][2]);
            tv.w = pack_h2(accT[r][3]);
            *reinterpret_cast<uint4*>(T + (size_t)grow * CDIM + c0) = tv;
            // H in fp32
            ulonglong2 h0, h1;
            h0.x = accR[r][0]; h0.y = accR[r][1]; h1.x = accR[r][2]; h1.y = accR[r][3];
            *reinterpret_cast<ulonglong2*>(H + (size_t)grow * CDIM + c0)     = h0;
            *reinterpret_cast<ulonglong2*>(H + (size_t)grow * CDIM + c0 + 4) = h1;
        }
    }
}

// ---------------- host-side CSR build helper ----------------
static void build_csr(const int* src, const int* dst, const float* attr, int E,
                      int* cnt, int* off, int* cur, int2* edges, int* bsum, int nNodes,
                      cudaStream_t s)
{
    const int n1 = nNodes + 1;
    const int nb = (n1 + 1023) / 1024;
    zero_int<<<(n1 + 1023) / 1024, 256, 0, s>>>(cnt, n1);
    hist_kernel<<<(E + 1023) / 1024, 256, 0, s>>>(dst, cnt, E);
    reduce_blk<<<nb, 256, 0, s>>>(cnt, bsum, n1);
    scan_partials<<<1, 512, 0, s>>>(bsum, nb);
    scan_final<<<nb, 256, 0, s>>>(cnt, bsum, off, cur, n1);
    permute_kernel<<<(E + 1023) / 1024, 256, 0, s>>>(src, dst, attr, cur, edges, E);
}

// ---------------- launch ----------------
extern "C" void kernel_launch(void* const* d_in, const int* in_sizes, int n_in,
                              void* d_out, int out_size)
{
    const float* x    = (const float*)d_in[0];
    const float* W1r  = (const float*)d_in[1];
    const float* W1n  = (const float*)d_in[2];
    const float* b1   = (const float*)d_in[3];
    const float* W2r  = (const float*)d_in[4];
    const float* W2n  = (const float*)d_in[5];
    const float* b2   = (const float*)d_in[6];
    const int*   psrc = (const int*)d_in[7];
    const int*   pdst = (const int*)d_in[8];
    const float* patt = (const float*)d_in[9];
    const int*   csrc = (const int*)d_in[10];
    const int*   cdst = (const int*)d_in[11];
    const float* catt = (const float*)d_in[12];
    const int*   usrc = (const int*)d_in[13];
    const int*   udst = (const int*)d_in[14];
    const float* uatt = (const float*)d_in[15];

    const int Ep = in_sizes[7];
    const int Ec = in_sizes[10];
    const int Eu = in_sizes[13];

    float* out = (float*)d_out;

    float *xc, *hb;
    __half* tb;
    cudaGetSymbolAddress((void**)&xc, g_xc);
    cudaGetSymbolAddress((void**)&tb, g_t);
    cudaGetSymbolAddress((void**)&hb, g_h);

    int *pcnt, *poff, *pcur, *ccnt, *coff, *ccur, *ucnt, *uoff, *ucur, *bsum;
    int2 *pedg, *cedg, *uedg;
    cudaGetSymbolAddress((void**)&pcnt, g_pool_cnt);
    cudaGetSymbolAddress((void**)&poff, g_pool_off);
    cudaGetSymbolAddress((void**)&pcur, g_pool_cur);
    cudaGetSymbolAddress((void**)&pedg, g_pool_edges);
    cudaGetSymbolAddress((void**)&ccnt, g_conv_cnt);
    cudaGetSymbolAddress((void**)&coff, g_conv_off);
    cudaGetSymbolAddress((void**)&ccur, g_conv_cur);
    cudaGetSymbolAddress((void**)&cedg, g_conv_edges);
    cudaGetSymbolAddress((void**)&ucnt, g_unp_cnt);
    cudaGetSymbolAddress((void**)&uoff, g_unp_off);
    cudaGetSymbolAddress((void**)&ucur, g_unp_cur);
    cudaGetSymbolAddress((void**)&uedg, g_unp_edges);
    cudaGetSymbolAddress((void**)&bsum, g_bsum);

    static cudaStream_t sB = nullptr, sC = nullptr;
    static cudaEvent_t ev0 = nullptr, evB = nullptr, evC = nullptr;
    if (sB == nullptr) {
        cudaStreamCreateWithFlags(&sB, cudaStreamNonBlocking);
        cudaStreamCreateWithFlags(&sC, cudaStreamNonBlocking);
        cudaEventCreateWithFlags(&ev0, cudaEventDisableTiming);
        cudaEventCreateWithFlags(&evB, cudaEventDisableTiming);
        cudaEventCreateWithFlags(&evC, cudaEventDisableTiming);
    }

    // fork: conv CSR on sB, unpool CSR on sC
    cudaEventRecord(ev0, 0);
    cudaStreamWaitEvent(sB, ev0, 0);
    cudaStreamWaitEvent(sC, ev0, 0);
    build_csr(csrc, cdst, catt, Ec, ccnt, coff, ccur, cedg, bsum + 512,  NCC, sB);
    cudaEventRecord(evB, sB);
    build_csr(usrc, udst, uatt, Eu, ucnt, uoff, ucur, uedg, bsum + 1024, NFF, sC);
    cudaEventRecord(evC, sC);

    // critical path
    build_csr(psrc, pdst, patt, Ep, pcnt, poff, pcur, pedg, bsum, NCC, 0);

    const int gthreadsC = NCC * 8;
    const int gthreadsF = NFF * 8;

    gather_kernel<false><<<(gthreadsC + 255) / 256, 256>>>(x, pedg, poff, xc, NCC);

    dual_gemm<<<(NCC + ROWS_PER_BLK - 1) / ROWS_PER_BLK, 256>>>(xc, W1n, W1r, b1, tb, hb, NCC);
    cudaStreamWaitEvent(0, evB, 0);
    gather_half<<<(gthreadsC + 255) / 256, 256>>>(tb, cedg, coff, hb, NCC);

    dual_gemm<<<(NCC + ROWS_PER_BLK - 1) / ROWS_PER_BLK, 256>>>(hb, W2n, W2r, b2, tb, xc, NCC);
    gather_half<<<(gthreadsC + 255) / 256, 256>>>(tb, cedg, coff, xc, NCC);

    cudaStreamWaitEvent(0, evC, 0);
    gather_kernel<false><<<(gthreadsF + 255) / 256, 256>>>(xc, uedg, uoff, out, NFF);
}

// round 9
// speedup vs baseline: 1.7099x; 1.2567x over previous
#include <cuda_runtime.h>
#include <cuda_fp16.h>
#include <cstdint>

#define NCC   100000   // n_coarse
#define NFF   400000   // n_fine
#define CDIM  64
#define EPMAX 1200000
#define ECMAX 1600000
#define EUMAX 1200000

typedef unsigned long long u64;

// ---------------- scratch ----------------
__device__ float  g_xc[(size_t)NCC * CDIM];
__device__ __half g_t [(size_t)NCC * CDIM];   // fp16 neighbor-transformed features
__device__ float  g_h [(size_t)NCC * CDIM];
__device__ __half g_wh[2][128 * 64];          // concat(Wn,Wr) as fp16, [n][k] layout

// CSR build scratch
__device__ int  g_pool_cnt[NCC + 4];
__device__ int  g_pool_off[NCC + 4];
__device__ int  g_pool_cur[NCC];
__device__ int2 g_pool_edges[EPMAX];

__device__ int  g_conv_cnt[NCC + 4];
__device__ int  g_conv_off[NCC + 4];
__device__ int  g_conv_cur[NCC];
__device__ int2 g_conv_edges[ECMAX];

__device__ int  g_unp_cnt[NFF + 4];
__device__ int  g_unp_off[NFF + 4];
__device__ int  g_unp_cur[NFF];
__device__ int2 g_unp_edges[EUMAX];

__device__ int  g_bsum[3 * 512];

// ---------------- helpers ----------------
__device__ __forceinline__ uint32_t f2toh2(float lo, float hi) {
    __half2 h = __floats2half2_rn(lo, hi);
    return *reinterpret_cast<uint32_t*>(&h);
}

// ---------------- small utility kernels ----------------
__global__ void zero_int(int* __restrict__ p, int n) {
    int i = (blockIdx.x * blockDim.x + threadIdx.x) * 4;
    if (i + 3 < n) {
        *reinterpret_cast<int4*>(p + i) = make_int4(0, 0, 0, 0);
    } else {
        for (int j = i; j < n && j < i + 4; j++) p[j] = 0;
    }
}

__global__ void hist_kernel(const int* __restrict__ dst, int* __restrict__ cnt, int E) {
    int i = (blockIdx.x * blockDim.x + threadIdx.x) * 4;
    if (i + 3 < E) {
        int4 d = *reinterpret_cast<const int4*>(dst + i);
        atomicAdd(&cnt[d.x], 1);
        atomicAdd(&cnt[d.y], 1);
        atomicAdd(&cnt[d.z], 1);
        atomicAdd(&cnt[d.w], 1);
    } else {
        for (int j = i; j < E && j < i + 4; j++) atomicAdd(&cnt[dst[j]], 1);
    }
}

__global__ void __launch_bounds__(256) reduce_blk(
    const int* __restrict__ cnt, int* __restrict__ bsum, int n)
{
    __shared__ int ws[8];
    int tid = threadIdx.x;
    int base = blockIdx.x * 1024 + tid * 4;
    int s = 0;
    if (base + 3 < n) {
        int4 v = *reinterpret_cast<const int4*>(cnt + base);
        s = v.x + v.y + v.z + v.w;
    } else {
        for (int j = base; j < n && j < base + 4; j++) s += cnt[j];
    }
#pragma unroll
    for (int o = 16; o; o >>= 1) s += __shfl_down_sync(0xffffffffu, s, o);
    if ((tid & 31) == 0) ws[tid >> 5] = s;
    __syncthreads();
    if (tid < 8) {
        int t = ws[tid];
#pragma unroll
        for (int o = 4; o; o >>= 1) t += __shfl_down_sync(0xffu, t, o);
        if (tid == 0) bsum[blockIdx.x] = t;
    }
}

__global__ void __launch_bounds__(512) scan_partials(int* __restrict__ bsum, int nb) {
    __shared__ int ws[16];
    int tid = threadIdx.x, lane = tid & 31, wid = tid >> 5;
    int v = (tid < nb) ? bsum[tid] : 0;
    int p = v;
#pragma unroll
    for (int o = 1; o < 32; o <<= 1) {
        int t = __shfl_up_sync(0xffffffffu, p, o);
        if (lane >= o) p += t;
    }
    if (lane == 31) ws[wid] = p;
    __syncthreads();
    if (tid < 16) {
        int t = ws[tid];
        int q = t;
#pragma unroll
        for (int o = 1; o < 16; o <<= 1) {
            int u = __shfl_up_sync(0xffffu, q, o);
            if (tid >= o) q += u;
        }
        ws[tid] = q - t;
    }
    __syncthreads();
    if (tid < nb) bsum[tid] = p - v + ws[wid];
}

__global__ void __launch_bounds__(256) scan_final(
    const int* __restrict__ cnt, const int* __restrict__ bsum,
    int* __restrict__ off, int* __restrict__ cursor, int n)
{
    __shared__ int ws[8];
    int tid = threadIdx.x, lane = tid & 31, wid = tid >> 5;
    int base = blockIdx.x * 1024 + tid * 4;
    int v0 = 0, v1 = 0, v2 = 0, v3 = 0;
    if (base + 3 < n) {
        int4 v = *reinterpret_cast<const int4*>(cnt + base);
        v0 = v.x; v1 = v.y; v2 = v.z; v3 = v.w;
    } else {
        if (base + 0 < n) v0 = cnt[base + 0];
        if (base + 1 < n) v1 = cnt[base + 1];
        if (base + 2 < n) v2 = cnt[base + 2];
        if (base + 3 < n) v3 = cnt[base + 3];
    }
    int s = v0 + v1 + v2 + v3;
    int p = s;
#pragma unroll
    for (int o = 1; o < 32; o <<= 1) {
        int t = __shfl_up_sync(0xffffffffu, p, o);
        if (lane >= o) p += t;
    }
    if (lane == 31) ws[wid] = p;
    __syncthreads();
    if (tid < 8) {
        int t = ws[tid];
        int q = t;
#pragma unroll
        for (int o = 1; o < 8; o <<= 1) {
            int u = __shfl_up_sync(0xffu, q, o);
            if (tid >= o) q += u;
        }
        ws[tid] = q - t;
    }
    __syncthreads();
    int excl = __ldg(bsum + blockIdx.x) + ws[wid] + (p - s);

    int o0 = excl, o1 = excl + v0, o2 = o1 + v1, o3 = o2 + v2;
    if (base + 3 < n) {
        *reinterpret_cast<int4*>(off + base) = make_int4(o0, o1, o2, o3);
    } else {
        if (base + 0 < n) off[base + 0] = o0;
        if (base + 1 < n) off[base + 1] = o1;
        if (base + 2 < n) off[base + 2] = o2;
        if (base + 3 < n) off[base + 3] = o3;
    }
    if (base + 0 < n - 1) cursor[base + 0] = o0;
    if (base + 1 < n - 1) cursor[base + 1] = o1;
    if (base + 2 < n - 1) cursor[base + 2] = o2;
    if (base + 3 < n - 1) cursor[base + 3] = o3;
}

__global__ void permute_kernel(const int* __restrict__ src, const int* __restrict__ dst,
                               const float* __restrict__ attr, int* __restrict__ cursor,
                               int2* __restrict__ edges, int E) {
    int i = (blockIdx.x * blockDim.x + threadIdx.x) * 4;
    if (i + 3 < E) {
        int4   sv = *reinterpret_cast<const int4*>(src + i);
        int4   dv = *reinterpret_cast<const int4*>(dst + i);
        float4 av = *reinterpret_cast<const float4*>(attr + i);
        int p0 = atomicAdd(&cursor[dv.x], 1);
        int p1 = atomicAdd(&cursor[dv.y], 1);
        int p2 = atomicAdd(&cursor[dv.z], 1);
        int p3 = atomicAdd(&cursor[dv.w], 1);
        edges[p0] = make_int2(sv.x, __float_as_int(av.x));
        edges[p1] = make_int2(sv.y, __float_as_int(av.y));
        edges[p2] = make_int2(sv.z, __float_as_int(av.z));
        edges[p3] = make_int2(sv.w, __float_as_int(av.w));
    } else {
        for (int j = i; j < E && j < i + 4; j++) {
            int p = atomicAdd(&cursor[dst[j]], 1);
            edges[p] = make_int2(src[j], __float_as_int(attr[j]));
        }
    }
}

// convert concat(Wn, Wr) [64][64] fp32 each -> Wh[n][k] fp16 (n in 0..127)
__global__ void wconvert(const float* __restrict__ Wn, const float* __restrict__ Wr,
                         __half* __restrict__ Wh)
{
    int idx = blockIdx.x * 256 + threadIdx.x;
    if (idx >= 128 * 64) return;
    int n = idx >> 6, k = idx & 63;
    float v = (n < 64) ? Wn[k * 64 + n] : Wr[k * 64 + (n - 64)];
    Wh[n * 64 + k] = __float2half(v);
}

// ---------------- CSR gather (fp32 features): 8 threads/node, 2x float4 ----------------
template <bool INIT_FROM_OUT>
__global__ void __launch_bounds__(256) gather_kernel(
    const float* __restrict__ feat,
    const int2*  __restrict__ edges,
    const int*   __restrict__ off,
    float*       __restrict__ outp,
    int n)
{
    int idx = blockIdx.x * blockDim.x + threadIdx.x;
    int node = idx >> 3;
    if (node >= n) return;
    int q = (idx & 7) << 3;

    int e0 = __ldg(off + node);
    int e1 = __ldg(off + node + 1);

    float* orow = outp + (size_t)node * CDIM + q;
    float4 acc0, acc1;
    if (INIT_FROM_OUT) {
        acc0 = *reinterpret_cast<const float4*>(orow);
        acc1 = *reinterpret_cast<const float4*>(orow + 4);
    } else {
        acc0 = make_float4(0.f, 0.f, 0.f, 0.f);
        acc1 = acc0;
    }

#pragma unroll 2
    for (int e = e0; e < e1; e++) {
        int2 ed = __ldg(edges + e);
        float w = __int_as_float(ed.y);
        const float4* p = reinterpret_cast<const float4*>(feat + (size_t)ed.x * CDIM + q);
        float4 v0 = __ldg(p);
        float4 v1 = __ldg(p + 1);
        acc0.x = fmaf(w, v0.x, acc0.x);
        acc0.y = fmaf(w, v0.y, acc0.y);
        acc0.z = fmaf(w, v0.z, acc0.z);
        acc0.w = fmaf(w, v0.w, acc0.w);
        acc1.x = fmaf(w, v1.x, acc1.x);
        acc1.y = fmaf(w, v1.y, acc1.y);
        acc1.z = fmaf(w, v1.z, acc1.z);
        acc1.w = fmaf(w, v1.w, acc1.w);
    }
    *reinterpret_cast<float4*>(orow)     = acc0;
    *reinterpret_cast<float4*>(orow + 4) = acc1;
}

// ---------------- CSR gather (fp16 features): 8 threads/node, 1x uint4 ----------------
__global__ void __launch_bounds__(256) gather_half(
    const __half* __restrict__ feat,
    const int2*   __restrict__ edges,
    const int*    __restrict__ off,
    float*        __restrict__ outp,
    int n)
{
    int idx = blockIdx.x * blockDim.x + threadIdx.x;
    int node = idx >> 3;
    if (node >= n) return;
    int q = (idx & 7) << 3;

    int e0 = __ldg(off + node);
    int e1 = __ldg(off + node + 1);

    float* orow = outp + (size_t)node * CDIM + q;
    float4 acc0 = *reinterpret_cast<const float4*>(orow);
    float4 acc1 = *reinterpret_cast<const float4*>(orow + 4);

#pragma unroll 2
    for (int e = e0; e < e1; e++) {
        int2 ed = __ldg(edges + e);
        float w = __int_as_float(ed.y);
        uint4 hv = __ldg(reinterpret_cast<const uint4*>(feat + ((size_t)ed.x << 6) + q));
        __half2 h0 = *reinterpret_cast<__half2*>(&hv.x);
        __half2 h1 = *reinterpret_cast<__half2*>(&hv.y);
        __half2 h2 = *reinterpret_cast<__half2*>(&hv.z);
        __half2 h3 = *reinterpret_cast<__half2*>(&hv.w);
        float2 f0 = __half22float2(h0);
        float2 f1 = __half22float2(h1);
        float2 f2 = __half22float2(h2);
        float2 f3 = __half22float2(h3);
        acc0.x = fmaf(w, f0.x, acc0.x);
        acc0.y = fmaf(w, f0.y, acc0.y);
        acc0.z = fmaf(w, f1.x, acc0.z);
        acc0.w = fmaf(w, f1.y, acc0.w);
        acc1.x = fmaf(w, f2.x, acc1.x);
        acc1.y = fmaf(w, f2.y, acc1.y);
        acc1.z = fmaf(w, f3.x, acc1.z);
        acc1.w = fmaf(w, f3.y, acc1.w);
    }
    *reinterpret_cast<float4*>(orow)     = acc0;
    *reinterpret_cast<float4*>(orow + 4) = acc1;
}

// ---------------- tensor-core dual GEMM: out[r][0:128] = A[r][:] @ Wcat ----------------
// mma.m16n8k16 f16 x f16 -> f32. Block = 256 thr = 8 warps x 16 rows = 128 rows.
// A fragments converted fp32->fp16 in-register from global; W fp16 in smem [n][k+pad].
#define ROWS_PER_BLK 128
#define WSTR 68   // smem k-stride (halves) for W: 2-way max bank conflicts

__device__ __forceinline__ void mma16816(
    float& c0, float& c1, float& c2, float& c3,
    uint32_t a0, uint32_t a1, uint32_t a2, uint32_t a3,
    uint32_t b0, uint32_t b1)
{
    asm volatile(
        "mma.sync.aligned.m16n8k16.row.col.f32.f16.f16.f32 "
        "{%0,%1,%2,%3}, {%4,%5,%6,%7}, {%8,%9}, {%0,%1,%2,%3};\n"
        : "+f"(c0), "+f"(c1), "+f"(c2), "+f"(c3)
        : "r"(a0), "r"(a1), "r"(a2), "r"(a3), "r"(b0), "r"(b1));
}

__global__ void __launch_bounds__(256, 2) dual_gemm_mma(
    const float* __restrict__ A,
    const __half* __restrict__ Wh,    // [128][64] n-major
    const float* __restrict__ bias,
    __half* __restrict__ T,
    float*  __restrict__ H,
    int N)
{
    __shared__ __half sW[128 * WSTR];

    const int t = threadIdx.x;

    // stage W: 128 x 64 halves -> stride-68 smem; 8 x uint2 (4 halves) per thread
#pragma unroll
    for (int i = 0; i < 8; i++) {
        int idx = t + 256 * i;        // uint2 units: 16 per n-row
        int n = idx >> 4, kq = (idx & 15) * 4;
        uint2 v = *reinterpret_cast<const uint2*>(Wh + n * 64 + kq);
        *reinterpret_cast<uint2*>(sW + n * WSTR + kq) = v;
    }
    __syncthreads();

    const int warp = t >> 5, lane = t & 31;
    const int gid = lane >> 2, tig = lane & 3;
    const int rA = blockIdx.x * ROWS_PER_BLK + warp * 16 + gid;
    const int rB = rA + 8;
    const int rAl = (rA < N) ? rA : (N - 1);
    const int rBl = (rB < N) ? rB : (N - 1);
    const float* Arow0 = A + (size_t)rAl * CDIM;
    const float* Arow8 = A + (size_t)rBl * CDIM;

    float acc[16][4];
#pragma unroll
    for (int nt = 0; nt < 16; nt++)
#pragma unroll
        for (int j = 0; j < 4; j++) acc[nt][j] = 0.f;

#pragma unroll
    for (int ks = 0; ks < 4; ks++) {
        const int c = ks * 16 + tig * 2;
        float2 f0 = *reinterpret_cast<const float2*>(Arow0 + c);
        float2 f1 = *reinterpret_cast<const float2*>(Arow8 + c);
        float2 f2 = *reinterpret_cast<const float2*>(Arow0 + c + 8);
        float2 f3 = *reinterpret_cast<const float2*>(Arow8 + c + 8);
        uint32_t a0 = f2toh2(f0.x, f0.y);
        uint32_t a1 = f2toh2(f1.x, f1.y);
        uint32_t a2 = f2toh2(f2.x, f2.y);
        uint32_t a3 = f2toh2(f3.x, f3.y);

        const __half* wb = sW + ks * 16 + tig * 2 + gid * WSTR;
#pragma unroll
        for (int nt = 0; nt < 16; nt++) {
            const __half* wp = wb + nt * 8 * WSTR;
            uint32_t b0 = *reinterpret_cast<const uint32_t*>(wp);
            uint32_t b1 = *reinterpret_cast<const uint32_t*>(wp + 8);
            mma16816(acc[nt][0], acc[nt][1], acc[nt][2], acc[nt][3],
                     a0, a1, a2, a3, b0, b1);
        }
    }

    // epilogue: ntiles 0-7 -> T fp16; 8-15 -> H fp32 (+bias)
#pragma unroll
    for (int nt = 0; nt < 8; nt++) {
        int col = nt * 8 + tig * 2;
        if (rA < N)
            *reinterpret_cast<uint32_t*>(T + (size_t)rA * CDIM + col) = f2toh2(acc[nt][0], acc[nt][1]);
        if (rB < N)
            *reinterpret_cast<uint32_t*>(T + (size_t)rB * CDIM + col) = f2toh2(acc[nt][2], acc[nt][3]);
    }
#pragma unroll
    for (int nt = 8; nt < 16; nt++) {
        int col = (nt - 8) * 8 + tig * 2;
        float2 bv = *reinterpret_cast<const float2*>(bias + col);
        if (rA < N) {
            float2 o; o.x = acc[nt][0] + bv.x; o.y = acc[nt][1] + bv.y;
            *reinterpret_cast<float2*>(H + (size_t)rA * CDIM + col) = o;
        }
        if (rB < N) {
            float2 o; o.x = acc[nt][2] + bv.x; o.y = acc[nt][3] + bv.y;
            *reinterpret_cast<float2*>(H + (size_t)rB * CDIM + col) = o;
        }
    }
}

// ---------------- host-side CSR build helper ----------------
static void build_csr(const int* src, const int* dst, const float* attr, int E,
                      int* cnt, int* off, int* cur, int2* edges, int* bsum, int nNodes,
                      cudaStream_t s)
{
    const int n1 = nNodes + 1;
    const int nb = (n1 + 1023) / 1024;
    zero_int<<<(n1 + 1023) / 1024, 256, 0, s>>>(cnt, n1);
    hist_kernel<<<(E + 1023) / 1024, 256, 0, s>>>(dst, cnt, E);
    reduce_blk<<<nb, 256, 0, s>>>(cnt, bsum, n1);
    scan_partials<<<1, 512, 0, s>>>(bsum, nb);
    scan_final<<<nb, 256, 0, s>>>(cnt, bsum, off, cur, n1);
    permute_kernel<<<(E + 1023) / 1024, 256, 0, s>>>(src, dst, attr, cur, edges, E);
}

// ---------------- launch ----------------
extern "C" void kernel_launch(void* const* d_in, const int* in_sizes, int n_in,
                              void* d_out, int out_size)
{
    const float* x    = (const float*)d_in[0];
    const float* W1r  = (const float*)d_in[1];
    const float* W1n  = (const float*)d_in[2];
    const float* b1   = (const float*)d_in[3];
    const float* W2r  = (const float*)d_in[4];
    const float* W2n  = (const float*)d_in[5];
    const float* b2   = (const float*)d_in[6];
    const int*   psrc = (const int*)d_in[7];
    const int*   pdst = (const int*)d_in[8];
    const float* patt = (const float*)d_in[9];
    const int*   csrc = (const int*)d_in[10];
    const int*   cdst = (const int*)d_in[11];
    const float* catt = (const float*)d_in[12];
    const int*   usrc = (const int*)d_in[13];
    const int*   udst = (const int*)d_in[14];
    const float* uatt = (const float*)d_in[15];

    const int Ep = in_sizes[7];
    const int Ec = in_sizes[10];
    const int Eu = in_sizes[13];

    float* out = (float*)d_out;

    float *xc, *hb;
    __half *tb, *wh;
    cudaGetSymbolAddress((void**)&xc, g_xc);
    cudaGetSymbolAddress((void**)&tb, g_t);
    cudaGetSymbolAddress((void**)&hb, g_h);
    cudaGetSymbolAddress((void**)&wh, g_wh);
    __half* w1h = wh;
    __half* w2h = wh + 128 * 64;

    int *pcnt, *poff, *pcur, *ccnt, *coff, *ccur, *ucnt, *uoff, *ucur, *bsum;
    int2 *pedg, *cedg, *uedg;
    cudaGetSymbolAddress((void**)&pcnt, g_pool_cnt);
    cudaGetSymbolAddress((void**)&poff, g_pool_off);
    cudaGetSymbolAddress((void**)&pcur, g_pool_cur);
    cudaGetSymbolAddress((void**)&pedg, g_pool_edges);
    cudaGetSymbolAddress((void**)&ccnt, g_conv_cnt);
    cudaGetSymbolAddress((void**)&coff, g_conv_off);
    cudaGetSymbolAddress((void**)&ccur, g_conv_cur);
    cudaGetSymbolAddress((void**)&cedg, g_conv_edges);
    cudaGetSymbolAddress((void**)&ucnt, g_unp_cnt);
    cudaGetSymbolAddress((void**)&uoff, g_unp_off);
    cudaGetSymbolAddress((void**)&ucur, g_unp_cur);
    cudaGetSymbolAddress((void**)&uedg, g_unp_edges);
    cudaGetSymbolAddress((void**)&bsum, g_bsum);

    static cudaStream_t sB = nullptr, sC = nullptr;
    static cudaEvent_t ev0 = nullptr, evB = nullptr, evC = nullptr;
    if (sB == nullptr) {
        cudaStreamCreateWithFlags(&sB, cudaStreamNonBlocking);
        cudaStreamCreateWithFlags(&sC, cudaStreamNonBlocking);
        cudaEventCreateWithFlags(&ev0, cudaEventDisableTiming);
        cudaEventCreateWithFlags(&evB, cudaEventDisableTiming);
        cudaEventCreateWithFlags(&evC, cudaEventDisableTiming);
    }

    // weight conversion (tiny, critical-path cost ~2us)
    wconvert<<<32, 256>>>(W1n, W1r, w1h);
    wconvert<<<32, 256>>>(W2n, W2r, w2h);

    // fork: conv CSR on sB, unpool CSR on sC
    cudaEventRecord(ev0, 0);
    cudaStreamWaitEvent(sB, ev0, 0);
    cudaStreamWaitEvent(sC, ev0, 0);
    build_csr(csrc, cdst, catt, Ec, ccnt, coff, ccur, cedg, bsum + 512,  NCC, sB);
    cudaEventRecord(evB, sB);
    build_csr(usrc, udst, uatt, Eu, ucnt, uoff, ucur, uedg, bsum + 1024, NFF, sC);
    cudaEventRecord(evC, sC);

    // critical path
    build_csr(psrc, pdst, patt, Ep, pcnt, poff, pcur, pedg, bsum, NCC, 0);

    const int gthreadsC = NCC * 8;
    const int gthreadsF = NFF * 8;
    const int gemmBlocks = (NCC + ROWS_PER_BLK - 1) / ROWS_PER_BLK;

    gather_kernel<false><<<(gthreadsC + 255) / 256, 256>>>(x, pedg, poff, xc, NCC);

    dual_gemm_mma<<<gemmBlocks, 256>>>(xc, w1h, b1, tb, hb, NCC);
    cudaStreamWaitEvent(0, evB, 0);
    gather_half<<<(gthreadsC + 255) / 256, 256>>>(tb, cedg, coff, hb, NCC);

    dual_gemm_mma<<<gemmBlocks, 256>>>(hb, w2h, b2, tb, xc, NCC);
    gather_half<<<(gthreadsC + 255) / 256, 256>>>(tb, cedg, coff, xc, NCC);

    cudaStreamWaitEvent(0, evC, 0);
    gather_kernel<false><<<(gthreadsF + 255) / 256, 256>>>(xc, uedg, uoff, out, NFF);
}

// round 10
// speedup vs baseline: 1.8383x; 1.0751x over previous
#include <cuda_runtime.h>
#include <cuda_fp16.h>
#include <cstdint>

#define NCC   100000   // n_coarse
#define NFF   400000   // n_fine
#define CDIM  64
#define EPMAX 1200000
#define ECMAX 1600000
#define EUMAX 1200000

typedef unsigned long long u64;

// ---------------- scratch ----------------
__device__ float  g_xc[(size_t)NCC * CDIM];   // pooled coarse features (fp32, GEMM input)
__device__ __half g_t [(size_t)NCC * CDIM];   // fp16 neighbor-transformed features
__device__ float  g_h [(size_t)NCC * CDIM];   // layer outputs (fp32)
__device__ __half g_xh[(size_t)NFF * CDIM];   // fp16 copy of input x
__device__ __half g_h2[(size_t)NCC * CDIM];   // fp16 layer-2 result (unpool input)
__device__ __half g_wh[2][128 * 64];          // concat(Wn,Wr) as fp16, [n][k] layout

// CSR build scratch
__device__ int  g_pool_cnt[NCC + 4];
__device__ int  g_pool_off[NCC + 4];
__device__ int  g_pool_cur[NCC];
__device__ int2 g_pool_edges[EPMAX];

__device__ int  g_conv_cnt[NCC + 4];
__device__ int  g_conv_off[NCC + 4];
__device__ int  g_conv_cur[NCC];
__device__ int2 g_conv_edges[ECMAX];

__device__ int  g_unp_cnt[NFF + 4];
__device__ int  g_unp_off[NFF + 4];
__device__ int  g_unp_cur[NFF];
__device__ int2 g_unp_edges[EUMAX];

__device__ int  g_bsum[3 * 512];

// ---------------- helpers ----------------
__device__ __forceinline__ uint32_t f2toh2(float lo, float hi) {
    __half2 h = __floats2half2_rn(lo, hi);
    return *reinterpret_cast<uint32_t*>(&h);
}

// ---------------- small utility kernels ----------------
__global__ void zero_int(int* __restrict__ p, int n) {
    int i = (blockIdx.x * blockDim.x + threadIdx.x) * 4;
    if (i + 3 < n) {
        *reinterpret_cast<int4*>(p + i) = make_int4(0, 0, 0, 0);
    } else {
        for (int j = i; j < n && j < i + 4; j++) p[j] = 0;
    }
}

__global__ void hist_kernel(const int* __restrict__ dst, int* __restrict__ cnt, int E) {
    int i = (blockIdx.x * blockDim.x + threadIdx.x) * 4;
    if (i + 3 < E) {
        int4 d = *reinterpret_cast<const int4*>(dst + i);
        atomicAdd(&cnt[d.x], 1);
        atomicAdd(&cnt[d.y], 1);
        atomicAdd(&cnt[d.z], 1);
        atomicAdd(&cnt[d.w], 1);
    } else {
        for (int j = i; j < E && j < i + 4; j++) atomicAdd(&cnt[dst[j]], 1);
    }
}

__global__ void __launch_bounds__(256) reduce_blk(
    const int* __restrict__ cnt, int* __restrict__ bsum, int n)
{
    __shared__ int ws[8];
    int tid = threadIdx.x;
    int base = blockIdx.x * 1024 + tid * 4;
    int s = 0;
    if (base + 3 < n) {
        int4 v = *reinterpret_cast<const int4*>(cnt + base);
        s = v.x + v.y + v.z + v.w;
    } else {
        for (int j = base; j < n && j < base + 4; j++) s += cnt[j];
    }
#pragma unroll
    for (int o = 16; o; o >>= 1) s += __shfl_down_sync(0xffffffffu, s, o);
    if ((tid & 31) == 0) ws[tid >> 5] = s;
    __syncthreads();
    if (tid < 8) {
        int t = ws[tid];
#pragma unroll
        for (int o = 4; o; o >>= 1) t += __shfl_down_sync(0xffu, t, o);
        if (tid == 0) bsum[blockIdx.x] = t;
    }
}

__global__ void __launch_bounds__(512) scan_partials(int* __restrict__ bsum, int nb) {
    __shared__ int ws[16];
    int tid = threadIdx.x, lane = tid & 31, wid = tid >> 5;
    int v = (tid < nb) ? bsum[tid] : 0;
    int p = v;
#pragma unroll
    for (int o = 1; o < 32; o <<= 1) {
        int t = __shfl_up_sync(0xffffffffu, p, o);
        if (lane >= o) p += t;
    }
    if (lane == 31) ws[wid] = p;
    __syncthreads();
    if (tid < 16) {
        int t = ws[tid];
        int q = t;
#pragma unroll
        for (int o = 1; o < 16; o <<= 1) {
            int u = __shfl_up_sync(0xffffu, q, o);
            if (tid >= o) q += u;
        }
        ws[tid] = q - t;
    }
    __syncthreads();
    if (tid < nb) bsum[tid] = p - v + ws[wid];
}

__global__ void __launch_bounds__(256) scan_final(
    const int* __restrict__ cnt, const int* __restrict__ bsum,
    int* __restrict__ off, int* __restrict__ cursor, int n)
{
    __shared__ int ws[8];
    int tid = threadIdx.x, lane = tid & 31, wid = tid >> 5;
    int base = blockIdx.x * 1024 + tid * 4;
    int v0 = 0, v1 = 0, v2 = 0, v3 = 0;
    if (base + 3 < n) {
        int4 v = *reinterpret_cast<const int4*>(cnt + base);
        v0 = v.x; v1 = v.y; v2 = v.z; v3 = v.w;
    } else {
        if (base + 0 < n) v0 = cnt[base + 0];
        if (base + 1 < n) v1 = cnt[base + 1];
        if (base + 2 < n) v2 = cnt[base + 2];
        if (base + 3 < n) v3 = cnt[base + 3];
    }
    int s = v0 + v1 + v2 + v3;
    int p = s;
#pragma unroll
    for (int o = 1; o < 32; o <<= 1) {
        int t = __shfl_up_sync(0xffffffffu, p, o);
        if (lane >= o) p += t;
    }
    if (lane == 31) ws[wid] = p;
    __syncthreads();
    if (tid < 8) {
        int t = ws[tid];
        int q = t;
#pragma unroll
        for (int o = 1; o < 8; o <<= 1) {
            int u = __shfl_up_sync(0xffu, q, o);
            if (tid >= o) q += u;
        }
        ws[tid] = q - t;
    }
    __syncthreads();
    int excl = __ldg(bsum + blockIdx.x) + ws[wid] + (p - s);

    int o0 = excl, o1 = excl + v0, o2 = o1 + v1, o3 = o2 + v2;
    if (base + 3 < n) {
        *reinterpret_cast<int4*>(off + base) = make_int4(o0, o1, o2, o3);
    } else {
        if (base + 0 < n) off[base + 0] = o0;
        if (base + 1 < n) off[base + 1] = o1;
        if (base + 2 < n) off[base + 2] = o2;
        if (base + 3 < n) off[base + 3] = o3;
    }
    if (base + 0 < n - 1) cursor[base + 0] = o0;
    if (base + 1 < n - 1) cursor[base + 1] = o1;
    if (base + 2 < n - 1) cursor[base + 2] = o2;
    if (base + 3 < n - 1) cursor[base + 3] = o3;
}

__global__ void permute_kernel(const int* __restrict__ src, const int* __restrict__ dst,
                               const float* __restrict__ attr, int* __restrict__ cursor,
                               int2* __restrict__ edges, int E) {
    int i = (blockIdx.x * blockDim.x + threadIdx.x) * 4;
    if (i + 3 < E) {
        int4   sv = *reinterpret_cast<const int4*>(src + i);
        int4   dv = *reinterpret_cast<const int4*>(dst + i);
        float4 av = *reinterpret_cast<const float4*>(attr + i);
        int p0 = atomicAdd(&cursor[dv.x], 1);
        int p1 = atomicAdd(&cursor[dv.y], 1);
        int p2 = atomicAdd(&cursor[dv.z], 1);
        int p3 = atomicAdd(&cursor[dv.w], 1);
        edges[p0] = make_int2(sv.x, __float_as_int(av.x));
        edges[p1] = make_int2(sv.y, __float_as_int(av.y));
        edges[p2] = make_int2(sv.z, __float_as_int(av.z));
        edges[p3] = make_int2(sv.w, __float_as_int(av.w));
    } else {
        for (int j = i; j < E && j < i + 4; j++) {
            int p = atomicAdd(&cursor[dst[j]], 1);
            edges[p] = make_int2(src[j], __float_as_int(attr[j]));
        }
    }
}

// convert concat(Wn, Wr) [64][64] fp32 each -> Wh[n][k] fp16 (n in 0..127)
__global__ void wconvert(const float* __restrict__ Wn, const float* __restrict__ Wr,
                         __half* __restrict__ Wh)
{
    int idx = blockIdx.x * 256 + threadIdx.x;
    if (idx >= 128 * 64) return;
    int n = idx >> 6, k = idx & 63;
    float v = (n < 64) ? Wn[k * 64 + n] : Wr[k * 64 + (n - 64)];
    Wh[n * 64 + k] = __float2half(v);
}

// convert fp32 array -> fp16 (8 floats / thread)
__global__ void __launch_bounds__(256) xconvert(
    const float* __restrict__ src, __half* __restrict__ dst, int n8)
{
    int i = blockIdx.x * blockDim.x + threadIdx.x;
    if (i >= n8) return;
    const float4* p = reinterpret_cast<const float4*>(src) + i * 2;
    float4 a = p[0], b = p[1];
    uint4 o;
    o.x = f2toh2(a.x, a.y);
    o.y = f2toh2(a.z, a.w);
    o.z = f2toh2(b.x, b.y);
    o.w = f2toh2(b.z, b.w);
    reinterpret_cast<uint4*>(dst)[i] = o;
}

// ---------------- CSR gather over fp16 features: 8 threads/node ----------------
// INIT: start from initp (fp32) row; else zero. OUT_HALF: write fp16, else fp32.
template <bool INIT, bool OUT_HALF>
__global__ void __launch_bounds__(256) gather_h(
    const __half* __restrict__ feat,
    const int2*   __restrict__ edges,
    const int*    __restrict__ off,
    const float*  __restrict__ initp,
    float*        __restrict__ outf,
    __half*       __restrict__ outh,
    int n)
{
    int idx = blockIdx.x * blockDim.x + threadIdx.x;
    int node = idx >> 3;
    if (node >= n) return;
    int q = (idx & 7) << 3;   // half/float index within row

    int e0 = __ldg(off + node);
    int e1 = __ldg(off + node + 1);

    float4 acc0, acc1;
    if (INIT) {
        const float* irow = initp + (size_t)node * CDIM + q;
        acc0 = *reinterpret_cast<const float4*>(irow);
        acc1 = *reinterpret_cast<const float4*>(irow + 4);
    } else {
        acc0 = make_float4(0.f, 0.f, 0.f, 0.f);
        acc1 = acc0;
    }

#pragma unroll 2
    for (int e = e0; e < e1; e++) {
        int2 ed = __ldg(edges + e);
        float w = __int_as_float(ed.y);
        uint4 hv = __ldg(reinterpret_cast<const uint4*>(feat + ((size_t)ed.x << 6) + q));
        __half2 h0 = *reinterpret_cast<__half2*>(&hv.x);
        __half2 h1 = *reinterpret_cast<__half2*>(&hv.y);
        __half2 h2 = *reinterpret_cast<__half2*>(&hv.z);
        __half2 h3 = *reinterpret_cast<__half2*>(&hv.w);
        float2 f0 = __half22float2(h0);
        float2 f1 = __half22float2(h1);
        float2 f2 = __half22float2(h2);
        float2 f3 = __half22float2(h3);
        acc0.x = fmaf(w, f0.x, acc0.x);
        acc0.y = fmaf(w, f0.y, acc0.y);
        acc0.z = fmaf(w, f1.x, acc0.z);
        acc0.w = fmaf(w, f1.y, acc0.w);
        acc1.x = fmaf(w, f2.x, acc1.x);
        acc1.y = fmaf(w, f2.y, acc1.y);
        acc1.z = fmaf(w, f3.x, acc1.z);
        acc1.w = fmaf(w, f3.y, acc1.w);
    }

    if (OUT_HALF) {
        uint4 o;
        o.x = f2toh2(acc0.x, acc0.y);
        o.y = f2toh2(acc0.z, acc0.w);
        o.z = f2toh2(acc1.x, acc1.y);
        o.w = f2toh2(acc1.z, acc1.w);
        *reinterpret_cast<uint4*>(outh + ((size_t)node << 6) + q) = o;
    } else {
        float* orow = outf + (size_t)node * CDIM + q;
        *reinterpret_cast<float4*>(orow)     = acc0;
        *reinterpret_cast<float4*>(orow + 4) = acc1;
    }
}

// ---------------- tensor-core dual GEMM ----------------
#define ROWS_PER_BLK 128
#define WSTR 68

__device__ __forceinline__ void mma16816(
    float& c0, float& c1, float& c2, float& c3,
    uint32_t a0, uint32_t a1, uint32_t a2, uint32_t a3,
    uint32_t b0, uint32_t b1)
{
    asm volatile(
        "mma.sync.aligned.m16n8k16.row.col.f32.f16.f16.f32 "
        "{%0,%1,%2,%3}, {%4,%5,%6,%7}, {%8,%9}, {%0,%1,%2,%3};\n"
        : "+f"(c0), "+f"(c1), "+f"(c2), "+f"(c3)
        : "r"(a0), "r"(a1), "r"(a2), "r"(a3), "r"(b0), "r"(b1));
}

__global__ void __launch_bounds__(256, 2) dual_gemm_mma(
    const float* __restrict__ A,
    const __half* __restrict__ Wh,
    const float* __restrict__ bias,
    __half* __restrict__ T,
    float*  __restrict__ H,
    int N)
{
    __shared__ __half sW[128 * WSTR];

    const int t = threadIdx.x;

#pragma unroll
    for (int i = 0; i < 8; i++) {
        int idx = t + 256 * i;
        int n = idx >> 4, kq = (idx & 15) * 4;
        uint2 v = *reinterpret_cast<const uint2*>(Wh + n * 64 + kq);
        *reinterpret_cast<uint2*>(sW + n * WSTR + kq) = v;
    }
    __syncthreads();

    const int warp = t >> 5, lane = t & 31;
    const int gid = lane >> 2, tig = lane & 3;
    const int rA = blockIdx.x * ROWS_PER_BLK + warp * 16 + gid;
    const int rB = rA + 8;
    const int rAl = (rA < N) ? rA : (N - 1);
    const int rBl = (rB < N) ? rB : (N - 1);
    const float* Arow0 = A + (size_t)rAl * CDIM;
    const float* Arow8 = A + (size_t)rBl * CDIM;

    float acc[16][4];
#pragma unroll
    for (int nt = 0; nt < 16; nt++)
#pragma unroll
        for (int j = 0; j < 4; j++) acc[nt][j] = 0.f;

#pragma unroll
    for (int ks = 0; ks < 4; ks++) {
        const int c = ks * 16 + tig * 2;
        float2 f0 = *reinterpret_cast<const float2*>(Arow0 + c);
        float2 f1 = *reinterpret_cast<const float2*>(Arow8 + c);
        float2 f2 = *reinterpret_cast<const float2*>(Arow0 + c + 8);
        float2 f3 = *reinterpret_cast<const float2*>(Arow8 + c + 8);
        uint32_t a0 = f2toh2(f0.x, f0.y);
        uint32_t a1 = f2toh2(f1.x, f1.y);
        uint32_t a2 = f2toh2(f2.x, f2.y);
        uint32_t a3 = f2toh2(f3.x, f3.y);

        const __half* wb = sW + ks * 16 + tig * 2 + gid * WSTR;
#pragma unroll
        for (int nt = 0; nt < 16; nt++) {
            const __half* wp = wb + nt * 8 * WSTR;
            uint32_t b0 = *reinterpret_cast<const uint32_t*>(wp);
            uint32_t b1 = *reinterpret_cast<const uint32_t*>(wp + 8);
            mma16816(acc[nt][0], acc[nt][1], acc[nt][2], acc[nt][3],
                     a0, a1, a2, a3, b0, b1);
        }
    }

#pragma unroll
    for (int nt = 0; nt < 8; nt++) {
        int col = nt * 8 + tig * 2;
        if (rA < N)
            *reinterpret_cast<uint32_t*>(T + (size_t)rA * CDIM + col) = f2toh2(acc[nt][0], acc[nt][1]);
        if (rB < N)
            *reinterpret_cast<uint32_t*>(T + (size_t)rB * CDIM + col) = f2toh2(acc[nt][2], acc[nt][3]);
    }
#pragma unroll
    for (int nt = 8; nt < 16; nt++) {
        int col = (nt - 8) * 8 + tig * 2;
        float2 bv = *reinterpret_cast<const float2*>(bias + col);
        if (rA < N) {
            float2 o; o.x = acc[nt][0] + bv.x; o.y = acc[nt][1] + bv.y;
            *reinterpret_cast<float2*>(H + (size_t)rA * CDIM + col) = o;
        }
        if (rB < N) {
            float2 o; o.x = acc[nt][2] + bv.x; o.y = acc[nt][3] + bv.y;
            *reinterpret_cast<float2*>(H + (size_t)rB * CDIM + col) = o;
        }
    }
}

// ---------------- host-side CSR build helper ----------------
static void build_csr(const int* src, const int* dst, const float* attr, int E,
                      int* cnt, int* off, int* cur, int2* edges, int* bsum, int nNodes,
                      cudaStream_t s)
{
    const int n1 = nNodes + 1;
    const int nb = (n1 + 1023) / 1024;
    zero_int<<<(n1 + 1023) / 1024, 256, 0, s>>>(cnt, n1);
    hist_kernel<<<(E + 1023) / 1024, 256, 0, s>>>(dst, cnt, E);
    reduce_blk<<<nb, 256, 0, s>>>(cnt, bsum, n1);
    scan_partials<<<1, 512, 0, s>>>(bsum, nb);
    scan_final<<<nb, 256, 0, s>>>(cnt, bsum, off, cur, n1);
    permute_kernel<<<(E + 1023) / 1024, 256, 0, s>>>(src, dst, attr, cur, edges, E);
}

// ---------------- launch ----------------
extern "C" void kernel_launch(void* const* d_in, const int* in_sizes, int n_in,
                              void* d_out, int out_size)
{
    const float* x    = (const float*)d_in[0];
    const float* W1r  = (const float*)d_in[1];
    const float* W1n  = (const float*)d_in[2];
    const float* b1   = (const float*)d_in[3];
    const float* W2r  = (const float*)d_in[4];
    const float* W2n  = (const float*)d_in[5];
    const float* b2   = (const float*)d_in[6];
    const int*   psrc = (const int*)d_in[7];
    const int*   pdst = (const int*)d_in[8];
    const float* patt = (const float*)d_in[9];
    const int*   csrc = (const int*)d_in[10];
    const int*   cdst = (const int*)d_in[11];
    const float* catt = (const float*)d_in[12];
    const int*   usrc = (const int*)d_in[13];
    const int*   udst = (const int*)d_in[14];
    const float* uatt = (const float*)d_in[15];

    const int Ep = in_sizes[7];
    const int Ec = in_sizes[10];
    const int Eu = in_sizes[13];

    float* out = (float*)d_out;

    float *xc, *hb;
    __half *tb, *wh, *xh, *h2;
    cudaGetSymbolAddress((void**)&xc, g_xc);
    cudaGetSymbolAddress((void**)&tb, g_t);
    cudaGetSymbolAddress((void**)&hb, g_h);
    cudaGetSymbolAddress((void**)&wh, g_wh);
    cudaGetSymbolAddress((void**)&xh, g_xh);
    cudaGetSymbolAddress((void**)&h2, g_h2);
    __half* w1h = wh;
    __half* w2h = wh + 128 * 64;

    int *pcnt, *poff, *pcur, *ccnt, *coff, *ccur, *ucnt, *uoff, *ucur, *bsum;
    int2 *pedg, *cedg, *uedg;
    cudaGetSymbolAddress((void**)&pcnt, g_pool_cnt);
    cudaGetSymbolAddress((void**)&poff, g_pool_off);
    cudaGetSymbolAddress((void**)&pcur, g_pool_cur);
    cudaGetSymbolAddress((void**)&pedg, g_pool_edges);
    cudaGetSymbolAddress((void**)&ccnt, g_conv_cnt);
    cudaGetSymbolAddress((void**)&coff, g_conv_off);
    cudaGetSymbolAddress((void**)&ccur, g_conv_cur);
    cudaGetSymbolAddress((void**)&cedg, g_conv_edges);
    cudaGetSymbolAddress((void**)&ucnt, g_unp_cnt);
    cudaGetSymbolAddress((void**)&uoff, g_unp_off);
    cudaGetSymbolAddress((void**)&ucur, g_unp_cur);
    cudaGetSymbolAddress((void**)&uedg, g_unp_edges);
    cudaGetSymbolAddress((void**)&bsum, g_bsum);

    static cudaStream_t sB = nullptr, sC = nullptr;
    static cudaEvent_t ev0 = nullptr, evB = nullptr, evC = nullptr, evX = nullptr;
    if (sB == nullptr) {
        cudaStreamCreateWithFlags(&sB, cudaStreamNonBlocking);
        cudaStreamCreateWithFlags(&sC, cudaStreamNonBlocking);
        cudaEventCreateWithFlags(&ev0, cudaEventDisableTiming);
        cudaEventCreateWithFlags(&evB, cudaEventDisableTiming);
        cudaEventCreateWithFlags(&evC, cudaEventDisableTiming);
        cudaEventCreateWithFlags(&evX, cudaEventDisableTiming);
    }

    // weight conversion (tiny)
    wconvert<<<32, 256>>>(W1n, W1r, w1h);
    wconvert<<<32, 256>>>(W2n, W2r, w2h);

    // fork: x->fp16 + conv CSR on sB; unpool CSR on sC
    cudaEventRecord(ev0, 0);
    cudaStreamWaitEvent(sB, ev0, 0);
    cudaStreamWaitEvent(sC, ev0, 0);
    const int n8 = NFF * CDIM / 8;
    xconvert<<<(n8 + 255) / 256, 256, 0, sB>>>(x, xh, n8);
    cudaEventRecord(evX, sB);
    build_csr(csrc, cdst, catt, Ec, ccnt, coff, ccur, cedg, bsum + 512,  NCC, sB);
    cudaEventRecord(evB, sB);
    build_csr(usrc, udst, uatt, Eu, ucnt, uoff, ucur, uedg, bsum + 1024, NFF, sC);
    cudaEventRecord(evC, sC);

    // critical path
    build_csr(psrc, pdst, patt, Ep, pcnt, poff, pcur, pedg, bsum, NCC, 0);

    const int gthreadsC = NCC * 8;
    const int gthreadsF = NFF * 8;
    const int gemmBlocks = (NCC + ROWS_PER_BLK - 1) / ROWS_PER_BLK;

    // pool: xc = gather(xh)  [fp16 -> fp32]
    cudaStreamWaitEvent(0, evX, 0);
    gather_h<false, false><<<(gthreadsC + 255) / 256, 256>>>(
        xh, pedg, poff, nullptr, xc, nullptr, NCC);

    // layer 1
    dual_gemm_mma<<<gemmBlocks, 256>>>(xc, w1h, b1, tb, hb, NCC);
    cudaStreamWaitEvent(0, evB, 0);
    gather_h<true, false><<<(gthreadsC + 255) / 256, 256>>>(
        tb, cedg, coff, hb, hb, nullptr, NCC);

    // layer 2 (H -> xc buffer; conv gather emits fp16 h2)
    dual_gemm_mma<<<gemmBlocks, 256>>>(hb, w2h, b2, tb, xc, NCC);
    gather_h<true, true><<<(gthreadsC + 255) / 256, 256>>>(
        tb, cedg, coff, xc, nullptr, h2, NCC);

    // unpool: out = gather(h2)  [fp16 -> fp32]
    cudaStreamWaitEvent(0, evC, 0);
    gather_h<false, false><<<(gthreadsF + 255) / 256, 256>>>(
        h2, uedg, uoff, nullptr, out, nullptr, NFF);
}

// round 11
// speedup vs baseline: 1.8602x; 1.0119x over previous
#include <cuda_runtime.h>
#include <cuda_fp16.h>
#include <cstdint>

#define NCC   100000   // n_coarse
#define NFF   400000   // n_fine
#define CDIM  64
#define EPMAX 1200000
#define ECMAX 1600000
#define EUMAX 1200000

typedef unsigned long long u64;

// ---------------- scratch ----------------
__device__ float  g_xc[(size_t)NCC * CDIM];   // pooled coarse features (fp32, GEMM input)
__device__ __half g_t [(size_t)NCC * CDIM];   // fp16 neighbor-transformed features
__device__ float  g_h [(size_t)NCC * CDIM];   // layer outputs (fp32)
__device__ __half g_xh[(size_t)NFF * CDIM];   // fp16 copy of input x
__device__ __half g_h2[(size_t)NCC * CDIM];   // fp16 layer-2 result (unpool input)
__device__ __half g_wh[2][128 * 64];          // concat(Wn,Wr) as fp16, [n][k] layout

// CSR build scratch (cnt buffer has lookback-state tail: +512 ints)
__device__ int  g_pool_cnt[NCC + 8 + 512];
__device__ int  g_pool_off[NCC + 4];
__device__ int  g_pool_cur[NCC];
__device__ int2 g_pool_edges[EPMAX];

__device__ int  g_conv_cnt[NCC + 8 + 512];
__device__ int  g_conv_off[NCC + 4];
__device__ int  g_conv_cur[NCC];
__device__ int2 g_conv_edges[ECMAX];

__device__ int  g_unp_cnt[NFF + 8 + 512];
__device__ int  g_unp_off[NFF + 4];
__device__ int  g_unp_cur[NFF];
__device__ int2 g_unp_edges[EUMAX];

// ---------------- helpers ----------------
__device__ __forceinline__ uint32_t f2toh2(float lo, float hi) {
    __half2 h = __floats2half2_rn(lo, hi);
    return *reinterpret_cast<uint32_t*>(&h);
}

// ---------------- small utility kernels ----------------
__global__ void zero_int(int* __restrict__ p, int n) {
    int i = (blockIdx.x * blockDim.x + threadIdx.x) * 4;
    if (i + 3 < n) {
        *reinterpret_cast<int4*>(p + i) = make_int4(0, 0, 0, 0);
    } else {
        for (int j = i; j < n && j < i + 4; j++) p[j] = 0;
    }
}

__global__ void hist_kernel(const int* __restrict__ dst, int* __restrict__ cnt, int E) {
    int i = (blockIdx.x * blockDim.x + threadIdx.x) * 4;
    if (i + 3 < E) {
        int4 d = *reinterpret_cast<const int4*>(dst + i);
        atomicAdd(&cnt[d.x], 1);
        atomicAdd(&cnt[d.y], 1);
        atomicAdd(&cnt[d.z], 1);
        atomicAdd(&cnt[d.w], 1);
    } else {
        for (int j = i; j < E && j < i + 4; j++) atomicAdd(&cnt[dst[j]], 1);
    }
}

// ---- single-pass exclusive scan with decoupled lookback ----
// 256 threads x 4 elems = 1024/block. state[blk]: (value<<2)|flag,
// flag 0=invalid 1=aggregate 2=inclusive-prefix. values <= E < 2^21, safe.
__global__ void __launch_bounds__(256) scan_lookback(
    const int* __restrict__ cnt, int* __restrict__ state,
    int* __restrict__ off, int* __restrict__ cursor, int n)
{
    __shared__ int ws[8];
    __shared__ int s_total;
    __shared__ int s_prefix;
    const int blk = blockIdx.x;
    const int tid = threadIdx.x, lane = tid & 31, wid = tid >> 5;
    const int base = blk * 1024 + tid * 4;

    int v0 = 0, v1 = 0, v2 = 0, v3 = 0;
    if (base + 3 < n) {
        int4 v = *reinterpret_cast<const int4*>(cnt + base);
        v0 = v.x; v1 = v.y; v2 = v.z; v3 = v.w;
    } else {
        if (base + 0 < n) v0 = cnt[base + 0];
        if (base + 1 < n) v1 = cnt[base + 1];
        if (base + 2 < n) v2 = cnt[base + 2];
        if (base + 3 < n) v3 = cnt[base + 3];
    }
    int s = v0 + v1 + v2 + v3;
    int p = s;
#pragma unroll
    for (int o = 1; o < 32; o <<= 1) {
        int t = __shfl_up_sync(0xffffffffu, p, o);
        if (lane >= o) p += t;
    }
    if (lane == 31) ws[wid] = p;
    __syncthreads();
    if (tid < 8) {
        int t = ws[tid];
        int q = t;
#pragma unroll
        for (int o = 1; o < 8; o <<= 1) {
            int u = __shfl_up_sync(0xffu, q, o);
            if (tid >= o) q += u;
        }
        ws[tid] = q - t;                // exclusive warp offset
        if (tid == 7) s_total = q;      // block total
    }
    __syncthreads();
    const int total = s_total;

    if (tid == 0) {
        if (blk == 0) {
            atomicExch(&state[0], (total << 2) | 2);
            s_prefix = 0;
        } else {
            atomicExch(&state[blk], (total << 2) | 1);
            int exc = 0;
            int j = blk - 1;
            while (j >= 0) {
                int st;
                do { st = atomicAdd(&state[j], 0); } while ((st & 3) == 0);
                exc += st >> 2;
                if ((st & 3) == 2) break;
                j--;
            }
            atomicExch(&state[blk], ((exc + total) << 2) | 2);
            s_prefix = exc;
        }
    }
    __syncthreads();

    const int excl = s_prefix + ws[wid] + (p - s);
    int o0 = excl, o1 = excl + v0, o2 = o1 + v1, o3 = o2 + v2;
    if (base + 3 < n) {
        *reinterpret_cast<int4*>(off + base) = make_int4(o0, o1, o2, o3);
    } else {
        if (base + 0 < n) off[base + 0] = o0;
        if (base + 1 < n) off[base + 1] = o1;
        if (base + 2 < n) off[base + 2] = o2;
        if (base + 3 < n) off[base + 3] = o3;
    }
    if (base + 0 < n - 1) cursor[base + 0] = o0;
    if (base + 1 < n - 1) cursor[base + 1] = o1;
    if (base + 2 < n - 1) cursor[base + 2] = o2;
    if (base + 3 < n - 1) cursor[base + 3] = o3;
}

__global__ void permute_kernel(const int* __restrict__ src, const int* __restrict__ dst,
                               const float* __restrict__ attr, int* __restrict__ cursor,
                               int2* __restrict__ edges, int E) {
    int i = (blockIdx.x * blockDim.x + threadIdx.x) * 4;
    if (i + 3 < E) {
        int4   sv = *reinterpret_cast<const int4*>(src + i);
        int4   dv = *reinterpret_cast<const int4*>(dst + i);
        float4 av = *reinterpret_cast<const float4*>(attr + i);
        int p0 = atomicAdd(&cursor[dv.x], 1);
        int p1 = atomicAdd(&cursor[dv.y], 1);
        int p2 = atomicAdd(&cursor[dv.z], 1);
        int p3 = atomicAdd(&cursor[dv.w], 1);
        edges[p0] = make_int2(sv.x, __float_as_int(av.x));
        edges[p1] = make_int2(sv.y, __float_as_int(av.y));
        edges[p2] = make_int2(sv.z, __float_as_int(av.z));
        edges[p3] = make_int2(sv.w, __float_as_int(av.w));
    } else {
        for (int j = i; j < E && j < i + 4; j++) {
            int p = atomicAdd(&cursor[dst[j]], 1);
            edges[p] = make_int2(src[j], __float_as_int(attr[j]));
        }
    }
}

// convert BOTH layers' concat(Wn, Wr) -> fp16 [n][k] in one launch
__global__ void wconvert2(const float* __restrict__ W1n, const float* __restrict__ W1r,
                          const float* __restrict__ W2n, const float* __restrict__ W2r,
                          __half* __restrict__ Wh)
{
    int idx = blockIdx.x * 256 + threadIdx.x;
    if (idx >= 2 * 128 * 64) return;
    int layer = idx >> 13;
    int r = idx & 8191;
    int n = r >> 6, k = r & 63;
    const float* Wn = layer ? W2n : W1n;
    const float* Wr = layer ? W2r : W1r;
    float v = (n < 64) ? Wn[k * 64 + n] : Wr[k * 64 + (n - 64)];
    Wh[idx] = __float2half(v);
}

// convert fp32 array -> fp16 (8 floats / thread)
__global__ void __launch_bounds__(256) xconvert(
    const float* __restrict__ src, __half* __restrict__ dst, int n8)
{
    int i = blockIdx.x * blockDim.x + threadIdx.x;
    if (i >= n8) return;
    const float4* p = reinterpret_cast<const float4*>(src) + i * 2;
    float4 a = p[0], b = p[1];
    uint4 o;
    o.x = f2toh2(a.x, a.y);
    o.y = f2toh2(a.z, a.w);
    o.z = f2toh2(b.x, b.y);
    o.w = f2toh2(b.z, b.w);
    reinterpret_cast<uint4*>(dst)[i] = o;
}

// ---------------- CSR gather over fp16 features: 8 threads/node ----------------
// INIT: start from initp (fp32) row; else zero.
// OUT_HALF: write fp16; STREAM: fp32 output with streaming stores (st.cs).
template <bool INIT, bool OUT_HALF, bool STREAM>
__global__ void __launch_bounds__(256) gather_h(
    const __half* __restrict__ feat,
    const int2*   __restrict__ edges,
    const int*    __restrict__ off,
    const float*  __restrict__ initp,
    float*        __restrict__ outf,
    __half*       __restrict__ outh,
    int n)
{
    int idx = blockIdx.x * blockDim.x + threadIdx.x;
    int node = idx >> 3;
    if (node >= n) return;
    int q = (idx & 7) << 3;   // half/float index within row

    int e0 = __ldg(off + node);
    int e1 = __ldg(off + node + 1);

    float4 acc0, acc1;
    if (INIT) {
        const float* irow = initp + (size_t)node * CDIM + q;
        acc0 = *reinterpret_cast<const float4*>(irow);
        acc1 = *reinterpret_cast<const float4*>(irow + 4);
    } else {
        acc0 = make_float4(0.f, 0.f, 0.f, 0.f);
        acc1 = acc0;
    }

#pragma unroll 2
    for (int e = e0; e < e1; e++) {
        int2 ed = __ldg(edges + e);
        float w = __int_as_float(ed.y);
        uint4 hv = __ldg(reinterpret_cast<const uint4*>(feat + ((size_t)ed.x << 6) + q));
        __half2 h0 = *reinterpret_cast<__half2*>(&hv.x);
        __half2 h1 = *reinterpret_cast<__half2*>(&hv.y);
        __half2 h2 = *reinterpret_cast<__half2*>(&hv.z);
        __half2 h3 = *reinterpret_cast<__half2*>(&hv.w);
        float2 f0 = __half22float2(h0);
        float2 f1 = __half22float2(h1);
        float2 f2 = __half22float2(h2);
        float2 f3 = __half22float2(h3);
        acc0.x = fmaf(w, f0.x, acc0.x);
        acc0.y = fmaf(w, f0.y, acc0.y);
        acc0.z = fmaf(w, f1.x, acc0.z);
        acc0.w = fmaf(w, f1.y, acc0.w);
        acc1.x = fmaf(w, f2.x, acc1.x);
        acc1.y = fmaf(w, f2.y, acc1.y);
        acc1.z = fmaf(w, f3.x, acc1.z);
        acc1.w = fmaf(w, f3.y, acc1.w);
    }

    if (OUT_HALF) {
        uint4 o;
        o.x = f2toh2(acc0.x, acc0.y);
        o.y = f2toh2(acc0.z, acc0.w);
        o.z = f2toh2(acc1.x, acc1.y);
        o.w = f2toh2(acc1.z, acc1.w);
        *reinterpret_cast<uint4*>(outh + ((size_t)node << 6) + q) = o;
    } else {
        float* orow = outf + (size_t)node * CDIM + q;
        if (STREAM) {
            __stcs(reinterpret_cast<float4*>(orow),     acc0);
            __stcs(reinterpret_cast<float4*>(orow + 4), acc1);
        } else {
            *reinterpret_cast<float4*>(orow)     = acc0;
            *reinterpret_cast<float4*>(orow + 4) = acc1;
        }
    }
}

// ---------------- tensor-core dual GEMM ----------------
#define ROWS_PER_BLK 128
#define WSTR 68

__device__ __forceinline__ void mma16816(
    float& c0, float& c1, float& c2, float& c3,
    uint32_t a0, uint32_t a1, uint32_t a2, uint32_t a3,
    uint32_t b0, uint32_t b1)
{
    asm volatile(
        "mma.sync.aligned.m16n8k16.row.col.f32.f16.f16.f32 "
        "{%0,%1,%2,%3}, {%4,%5,%6,%7}, {%8,%9}, {%0,%1,%2,%3};\n"
        : "+f"(c0), "+f"(c1), "+f"(c2), "+f"(c3)
        : "r"(a0), "r"(a1), "r"(a2), "r"(a3), "r"(b0), "r"(b1));
}

__global__ void __launch_bounds__(256, 2) dual_gemm_mma(
    const float* __restrict__ A,
    const __half* __restrict__ Wh,
    const float* __restrict__ bias,
    __half* __restrict__ T,
    float*  __restrict__ H,
    int N)
{
    __shared__ __half sW[128 * WSTR];

    const int t = threadIdx.x;

#pragma unroll
    for (int i = 0; i < 8; i++) {
        int idx = t + 256 * i;
        int n = idx >> 4, kq = (idx & 15) * 4;
        uint2 v = *reinterpret_cast<const uint2*>(Wh + n * 64 + kq);
        *reinterpret_cast<uint2*>(sW + n * WSTR + kq) = v;
    }
    __syncthreads();

    const int warp = t >> 5, lane = t & 31;
    const int gid = lane >> 2, tig = lane & 3;
    const int rA = blockIdx.x * ROWS_PER_BLK + warp * 16 + gid;
    const int rB = rA + 8;
    const int rAl = (rA < N) ? rA : (N - 1);
    const int rBl = (rB < N) ? rB : (N - 1);
    const float* Arow0 = A + (size_t)rAl * CDIM;
    const float* Arow8 = A + (size_t)rBl * CDIM;

    float acc[16][4];
#pragma unroll
    for (int nt = 0; nt < 16; nt++)
#pragma unroll
        for (int j = 0; j < 4; j++) acc[nt][j] = 0.f;

#pragma unroll
    for (int ks = 0; ks < 4; ks++) {
        const int c = ks * 16 + tig * 2;
        float2 f0 = *reinterpret_cast<const float2*>(Arow0 + c);
        float2 f1 = *reinterpret_cast<const float2*>(Arow8 + c);
        float2 f2 = *reinterpret_cast<const float2*>(Arow0 + c + 8);
        float2 f3 = *reinterpret_cast<const float2*>(Arow8 + c + 8);
        uint32_t a0 = f2toh2(f0.x, f0.y);
        uint32_t a1 = f2toh2(f1.x, f1.y);
        uint32_t a2 = f2toh2(f2.x, f2.y);
        uint32_t a3 = f2toh2(f3.x, f3.y);

        const __half* wb = sW + ks * 16 + tig * 2 + gid * WSTR;
#pragma unroll
        for (int nt = 0; nt < 16; nt++) {
            const __half* wp = wb + nt * 8 * WSTR;
            uint32_t b0 = *reinterpret_cast<const uint32_t*>(wp);
            uint32_t b1 = *reinterpret_cast<const uint32_t*>(wp + 8);
            mma16816(acc[nt][0], acc[nt][1], acc[nt][2], acc[nt][3],
                     a0, a1, a2, a3, b0, b1);
        }
    }

#pragma unroll
    for (int nt = 0; nt < 8; nt++) {
        int col = nt * 8 + tig * 2;
        if (rA < N)
            *reinterpret_cast<uint32_t*>(T + (size_t)rA * CDIM + col) = f2toh2(acc[nt][0], acc[nt][1]);
        if (rB < N)
            *reinterpret_cast<uint32_t*>(T + (size_t)rB * CDIM + col) = f2toh2(acc[nt][2], acc[nt][3]);
    }
#pragma unroll
    for (int nt = 8; nt < 16; nt++) {
        int col = (nt - 8) * 8 + tig * 2;
        float2 bv = *reinterpret_cast<const float2*>(bias + col);
        if (rA < N) {
            float2 o; o.x = acc[nt][0] + bv.x; o.y = acc[nt][1] + bv.y;
            *reinterpret_cast<float2*>(H + (size_t)rA * CDIM + col) = o;
        }
        if (rB < N) {
            float2 o; o.x = acc[nt][2] + bv.x; o.y = acc[nt][3] + bv.y;
            *reinterpret_cast<float2*>(H + (size_t)rB * CDIM + col) = o;
        }
    }
}

// ---------------- host-side CSR build helper (4 kernels) ----------------
static void build_csr(const int* src, const int* dst, const float* attr, int E,
                      int* cnt, int* off, int* cur, int2* edges, int nNodes,
                      cudaStream_t s)
{
    const int n1 = nNodes + 1;
    const int nb = (n1 + 1023) / 1024;
    const int stateOff = (n1 + 3) & ~3;       // 16B-aligned state tail
    int* state = cnt + stateOff;
    // zero cnt + lookback state in one pass
    zero_int<<<(stateOff + nb + 1023) / 1024, 256, 0, s>>>(cnt, stateOff + nb);
    hist_kernel<<<(E + 1023) / 1024, 256, 0, s>>>(dst, cnt, E);
    scan_lookback<<<nb, 256, 0, s>>>(cnt, state, off, cur, n1);
    permute_kernel<<<(E + 1023) / 1024, 256, 0, s>>>(src, dst, attr, cur, edges, E);
}

// ---------------- launch ----------------
extern "C" void kernel_launch(void* const* d_in, const int* in_sizes, int n_in,
                              void* d_out, int out_size)
{
    const float* x    = (const float*)d_in[0];
    const float* W1r  = (const float*)d_in[1];
    const float* W1n  = (const float*)d_in[2];
    const float* b1   = (const float*)d_in[3];
    const float* W2r  = (const float*)d_in[4];
    const float* W2n  = (const float*)d_in[5];
    const float* b2   = (const float*)d_in[6];
    const int*   psrc = (const int*)d_in[7];
    const int*   pdst = (const int*)d_in[8];
    const float* patt = (const float*)d_in[9];
    const int*   csrc = (const int*)d_in[10];
    const int*   cdst = (const int*)d_in[11];
    const float* catt = (const float*)d_in[12];
    const int*   usrc = (const int*)d_in[13];
    const int*   udst = (const int*)d_in[14];
    const float* uatt = (const float*)d_in[15];

    const int Ep = in_sizes[7];
    const int Ec = in_sizes[10];
    const int Eu = in_sizes[13];

    float* out = (float*)d_out;

    float *xc, *hb;
    __half *tb, *wh, *xh, *h2;
    cudaGetSymbolAddress((void**)&xc, g_xc);
    cudaGetSymbolAddress((void**)&tb, g_t);
    cudaGetSymbolAddress((void**)&hb, g_h);
    cudaGetSymbolAddress((void**)&wh, g_wh);
    cudaGetSymbolAddress((void**)&xh, g_xh);
    cudaGetSymbolAddress((void**)&h2, g_h2);
    __half* w1h = wh;
    __half* w2h = wh + 128 * 64;

    int *pcnt, *poff, *pcur, *ccnt, *coff, *ccur, *ucnt, *uoff, *ucur;
    int2 *pedg, *cedg, *uedg;
    cudaGetSymbolAddress((void**)&pcnt, g_pool_cnt);
    cudaGetSymbolAddress((void**)&poff, g_pool_off);
    cudaGetSymbolAddress((void**)&pcur, g_pool_cur);
    cudaGetSymbolAddress((void**)&pedg, g_pool_edges);
    cudaGetSymbolAddress((void**)&ccnt, g_conv_cnt);
    cudaGetSymbolAddress((void**)&coff, g_conv_off);
    cudaGetSymbolAddress((void**)&ccur, g_conv_cur);
    cudaGetSymbolAddress((void**)&cedg, g_conv_edges);
    cudaGetSymbolAddress((void**)&ucnt, g_unp_cnt);
    cudaGetSymbolAddress((void**)&uoff, g_unp_off);
    cudaGetSymbolAddress((void**)&ucur, g_unp_cur);
    cudaGetSymbolAddress((void**)&uedg, g_unp_edges);

    static cudaStream_t sB = nullptr, sC = nullptr;
    static cudaEvent_t ev0 = nullptr, evB = nullptr, evC = nullptr, evX = nullptr;
    if (sB == nullptr) {
        cudaStreamCreateWithFlags(&sB, cudaStreamNonBlocking);
        cudaStreamCreateWithFlags(&sC, cudaStreamNonBlocking);
        cudaEventCreateWithFlags(&ev0, cudaEventDisableTiming);
        cudaEventCreateWithFlags(&evB, cudaEventDisableTiming);
        cudaEventCreateWithFlags(&evC, cudaEventDisableTiming);
        cudaEventCreateWithFlags(&evX, cudaEventDisableTiming);
    }

    // weight conversion: one launch for both layers
    wconvert2<<<64, 256>>>(W1n, W1r, W2n, W2r, wh);

    // fork: x->fp16 + conv CSR on sB; unpool CSR on sC
    cudaEventRecord(ev0, 0);
    cudaStreamWaitEvent(sB, ev0, 0);
    cudaStreamWaitEvent(sC, ev0, 0);
    const int n8 = NFF * CDIM / 8;
    xconvert<<<(n8 + 255) / 256, 256, 0, sB>>>(x, xh, n8);
    cudaEventRecord(evX, sB);
    build_csr(csrc, cdst, catt, Ec, ccnt, coff, ccur, cedg, NCC, sB);
    cudaEventRecord(evB, sB);
    build_csr(usrc, udst, uatt, Eu, ucnt, uoff, ucur, uedg, NFF, sC);
    cudaEventRecord(evC, sC);

    // critical path
    build_csr(psrc, pdst, patt, Ep, pcnt, poff, pcur, pedg, NCC, 0);

    const int gthreadsC = NCC * 8;
    const int gthreadsF = NFF * 8;
    const int gemmBlocks = (NCC + ROWS_PER_BLK - 1) / ROWS_PER_BLK;

    // pool: xc = gather(xh)  [fp16 -> fp32]
    cudaStreamWaitEvent(0, evX, 0);
    gather_h<false, false, false><<<(gthreadsC + 255) / 256, 256>>>(
        xh, pedg, poff, nullptr, xc, nullptr, NCC);

    // layer 1
    dual_gemm_mma<<<gemmBlocks, 256>>>(xc, w1h, b1, tb, hb, NCC);
    cudaStreamWaitEvent(0, evB, 0);
    gather_h<true, false, false><<<(gthreadsC + 255) / 256, 256>>>(
        tb, cedg, coff, hb, hb, nullptr, NCC);

    // layer 2 (H -> xc buffer; conv gather emits fp16 h2)
    dual_gemm_mma<<<gemmBlocks, 256>>>(hb, w2h, b2, tb, xc, NCC);
    gather_h<true, true, false><<<(gthreadsC + 255) / 256, 256>>>(
        tb, cedg, coff, xc, nullptr, h2, NCC);

    // unpool: out = gather(h2)  [fp16 -> fp32, streaming stores]
    cudaStreamWaitEvent(0, evC, 0);
    gather_h<false, false, true><<<(gthreadsF + 255) / 256, 256>>>(
        h2, uedg, uoff, nullptr, out, nullptr, NFF);
}

// round 12
// speedup vs baseline: 1.9005x; 1.0217x over previous
#include <cuda_runtime.h>
#include <cuda_fp16.h>
#include <cstdint>

#define NCC   100000   // n_coarse
#define NFF   400000   // n_fine
#define CDIM  64
#define EPMAX 1200000
#define ECMAX 1600000
#define EUMAX 1200000

typedef unsigned long long u64;

// ---------------- scratch ----------------
__device__ __half g_a [(size_t)NCC * CDIM];   // cycled fp16 feature buffer (xc / h / h2)
__device__ __half g_t [(size_t)NCC * CDIM];   // fp16 neighbor-transformed features
__device__ float  g_h [(size_t)NCC * CDIM];   // fp32 root+bias (H) buffer
__device__ __half g_xh[(size_t)NFF * CDIM];   // fp16 copy of input x
__device__ __half g_wh[2][128 * 64];          // concat(Wn,Wr) as fp16, [n][k] layout

// CSR build scratch (cnt buffer has lookback-state tail)
__device__ int  g_pool_cnt[NCC + 8 + 512];
__device__ int  g_pool_off[NCC + 4];
__device__ int  g_pool_cur[NCC];
__device__ int2 g_pool_edges[EPMAX];

__device__ int  g_conv_cnt[NCC + 8 + 512];
__device__ int  g_conv_off[NCC + 4];
__device__ int  g_conv_cur[NCC];
__device__ int2 g_conv_edges[ECMAX];

__device__ int  g_unp_cnt[NFF + 8 + 512];
__device__ int  g_unp_off[NFF + 4];
__device__ int  g_unp_cur[NFF];
__device__ int2 g_unp_edges[EUMAX];

// ---------------- helpers ----------------
__device__ __forceinline__ uint32_t f2toh2(float lo, float hi) {
    __half2 h = __floats2half2_rn(lo, hi);
    return *reinterpret_cast<uint32_t*>(&h);
}

// ---------------- small utility kernels ----------------
__global__ void zero_int(int* __restrict__ p, int n) {
    int i = (blockIdx.x * blockDim.x + threadIdx.x) * 4;
    if (i + 3 < n) {
        *reinterpret_cast<int4*>(p + i) = make_int4(0, 0, 0, 0);
    } else {
        for (int j = i; j < n && j < i + 4; j++) p[j] = 0;
    }
}

__global__ void hist_kernel(const int* __restrict__ dst, int* __restrict__ cnt, int E) {
    int i = (blockIdx.x * blockDim.x + threadIdx.x) * 4;
    if (i + 3 < E) {
        int4 d = *reinterpret_cast<const int4*>(dst + i);
        atomicAdd(&cnt[d.x], 1);
        atomicAdd(&cnt[d.y], 1);
        atomicAdd(&cnt[d.z], 1);
        atomicAdd(&cnt[d.w], 1);
    } else {
        for (int j = i; j < E && j < i + 4; j++) atomicAdd(&cnt[dst[j]], 1);
    }
}

// ---- single-pass exclusive scan with decoupled lookback ----
__global__ void __launch_bounds__(256) scan_lookback(
    const int* __restrict__ cnt, int* __restrict__ state,
    int* __restrict__ off, int* __restrict__ cursor, int n)
{
    __shared__ int ws[8];
    __shared__ int s_total;
    __shared__ int s_prefix;
    const int blk = blockIdx.x;
    const int tid = threadIdx.x, lane = tid & 31, wid = tid >> 5;
    const int base = blk * 1024 + tid * 4;

    int v0 = 0, v1 = 0, v2 = 0, v3 = 0;
    if (base + 3 < n) {
        int4 v = *reinterpret_cast<const int4*>(cnt + base);
        v0 = v.x; v1 = v.y; v2 = v.z; v3 = v.w;
    } else {
        if (base + 0 < n) v0 = cnt[base + 0];
        if (base + 1 < n) v1 = cnt[base + 1];
        if (base + 2 < n) v2 = cnt[base + 2];
        if (base + 3 < n) v3 = cnt[base + 3];
    }
    int s = v0 + v1 + v2 + v3;
    int p = s;
#pragma unroll
    for (int o = 1; o < 32; o <<= 1) {
        int t = __shfl_up_sync(0xffffffffu, p, o);
        if (lane >= o) p += t;
    }
    if (lane == 31) ws[wid] = p;
    __syncthreads();
    if (tid < 8) {
        int t = ws[tid];
        int q = t;
#pragma unroll
        for (int o = 1; o < 8; o <<= 1) {
            int u = __shfl_up_sync(0xffu, q, o);
            if (tid >= o) q += u;
        }
        ws[tid] = q - t;
        if (tid == 7) s_total = q;
    }
    __syncthreads();
    const int total = s_total;

    if (tid == 0) {
        if (blk == 0) {
            atomicExch(&state[0], (total << 2) | 2);
            s_prefix = 0;
        } else {
            atomicExch(&state[blk], (total << 2) | 1);
            int exc = 0;
            int j = blk - 1;
            while (j >= 0) {
                int st;
                do { st = atomicAdd(&state[j], 0); } while ((st & 3) == 0);
                exc += st >> 2;
                if ((st & 3) == 2) break;
                j--;
            }
            atomicExch(&state[blk], ((exc + total) << 2) | 2);
            s_prefix = exc;
        }
    }
    __syncthreads();

    const int excl = s_prefix + ws[wid] + (p - s);
    int o0 = excl, o1 = excl + v0, o2 = o1 + v1, o3 = o2 + v2;
    if (base + 3 < n) {
        *reinterpret_cast<int4*>(off + base) = make_int4(o0, o1, o2, o3);
    } else {
        if (base + 0 < n) off[base + 0] = o0;
        if (base + 1 < n) off[base + 1] = o1;
        if (base + 2 < n) off[base + 2] = o2;
        if (base + 3 < n) off[base + 3] = o3;
    }
    if (base + 0 < n - 1) cursor[base + 0] = o0;
    if (base + 1 < n - 1) cursor[base + 1] = o1;
    if (base + 2 < n - 1) cursor[base + 2] = o2;
    if (base + 3 < n - 1) cursor[base + 3] = o3;
}

__global__ void permute_kernel(const int* __restrict__ src, const int* __restrict__ dst,
                               const float* __restrict__ attr, int* __restrict__ cursor,
                               int2* __restrict__ edges, int E) {
    int i = (blockIdx.x * blockDim.x + threadIdx.x) * 4;
    if (i + 3 < E) {
        int4   sv = *reinterpret_cast<const int4*>(src + i);
        int4   dv = *reinterpret_cast<const int4*>(dst + i);
        float4 av = *reinterpret_cast<const float4*>(attr + i);
        int p0 = atomicAdd(&cursor[dv.x], 1);
        int p1 = atomicAdd(&cursor[dv.y], 1);
        int p2 = atomicAdd(&cursor[dv.z], 1);
        int p3 = atomicAdd(&cursor[dv.w], 1);
        edges[p0] = make_int2(sv.x, __float_as_int(av.x));
        edges[p1] = make_int2(sv.y, __float_as_int(av.y));
        edges[p2] = make_int2(sv.z, __float_as_int(av.z));
        edges[p3] = make_int2(sv.w, __float_as_int(av.w));
    } else {
        for (int j = i; j < E && j < i + 4; j++) {
            int p = atomicAdd(&cursor[dst[j]], 1);
            edges[p] = make_int2(src[j], __float_as_int(attr[j]));
        }
    }
}

// convert BOTH layers' concat(Wn, Wr) -> fp16 [n][k] in one launch
__global__ void wconvert2(const float* __restrict__ W1n, const float* __restrict__ W1r,
                          const float* __restrict__ W2n, const float* __restrict__ W2r,
                          __half* __restrict__ Wh)
{
    int idx = blockIdx.x * 256 + threadIdx.x;
    if (idx >= 2 * 128 * 64) return;
    int layer = idx >> 13;
    int r = idx & 8191;
    int n = r >> 6, k = r & 63;
    const float* Wn = layer ? W2n : W1n;
    const float* Wr = layer ? W2r : W1r;
    float v = (n < 64) ? Wn[k * 64 + n] : Wr[k * 64 + (n - 64)];
    Wh[idx] = __float2half(v);
}

// convert fp32 array -> fp16 (8 floats / thread)
__global__ void __launch_bounds__(256) xconvert(
    const float* __restrict__ src, __half* __restrict__ dst, int n8)
{
    int i = blockIdx.x * blockDim.x + threadIdx.x;
    if (i >= n8) return;
    const float4* p = reinterpret_cast<const float4*>(src) + i * 2;
    float4 a = p[0], b = p[1];
    uint4 o;
    o.x = f2toh2(a.x, a.y);
    o.y = f2toh2(a.z, a.w);
    o.z = f2toh2(b.x, b.y);
    o.w = f2toh2(b.z, b.w);
    reinterpret_cast<uint4*>(dst)[i] = o;
}

// ---------------- CSR gather over fp16 features: 8 threads/node ----------------
// INIT: start from initp (fp32) row; else zero.
// OUT_HALF: write fp16; else fp32 (STREAM -> st.cs).
template <bool INIT, bool OUT_HALF, bool STREAM>
__global__ void __launch_bounds__(256) gather_h(
    const __half* __restrict__ feat,
    const int2*   __restrict__ edges,
    const int*    __restrict__ off,
    const float*  __restrict__ initp,
    float*        __restrict__ outf,
    __half*       __restrict__ outh,
    int n)
{
    int idx = blockIdx.x * blockDim.x + threadIdx.x;
    int node = idx >> 3;
    if (node >= n) return;
    int q = (idx & 7) << 3;

    int e0 = __ldg(off + node);
    int e1 = __ldg(off + node + 1);

    float4 acc0, acc1;
    if (INIT) {
        const float* irow = initp + (size_t)node * CDIM + q;
        acc0 = *reinterpret_cast<const float4*>(irow);
        acc1 = *reinterpret_cast<const float4*>(irow + 4);
    } else {
        acc0 = make_float4(0.f, 0.f, 0.f, 0.f);
        acc1 = acc0;
    }

#pragma unroll 2
    for (int e = e0; e < e1; e++) {
        int2 ed = __ldg(edges + e);
        float w = __int_as_float(ed.y);
        uint4 hv = __ldg(reinterpret_cast<const uint4*>(feat + ((size_t)ed.x << 6) + q));
        __half2 h0 = *reinterpret_cast<__half2*>(&hv.x);
        __half2 h1 = *reinterpret_cast<__half2*>(&hv.y);
        __half2 h2 = *reinterpret_cast<__half2*>(&hv.z);
        __half2 h3 = *reinterpret_cast<__half2*>(&hv.w);
        float2 f0 = __half22float2(h0);
        float2 f1 = __half22float2(h1);
        float2 f2 = __half22float2(h2);
        float2 f3 = __half22float2(h3);
        acc0.x = fmaf(w, f0.x, acc0.x);
        acc0.y = fmaf(w, f0.y, acc0.y);
        acc0.z = fmaf(w, f1.x, acc0.z);
        acc0.w = fmaf(w, f1.y, acc0.w);
        acc1.x = fmaf(w, f2.x, acc1.x);
        acc1.y = fmaf(w, f2.y, acc1.y);
        acc1.z = fmaf(w, f3.x, acc1.z);
        acc1.w = fmaf(w, f3.y, acc1.w);
    }

    if (OUT_HALF) {
        uint4 o;
        o.x = f2toh2(acc0.x, acc0.y);
        o.y = f2toh2(acc0.z, acc0.w);
        o.z = f2toh2(acc1.x, acc1.y);
        o.w = f2toh2(acc1.z, acc1.w);
        *reinterpret_cast<uint4*>(outh + ((size_t)node << 6) + q) = o;
    } else {
        float* orow = outf + (size_t)node * CDIM + q;
        if (STREAM) {
            __stcs(reinterpret_cast<float4*>(orow),     acc0);
            __stcs(reinterpret_cast<float4*>(orow + 4), acc1);
        } else {
            *reinterpret_cast<float4*>(orow)     = acc0;
            *reinterpret_cast<float4*>(orow + 4) = acc1;
        }
    }
}

// ---------------- tensor-core dual GEMM (fp16 A direct load) ----------------
#define ROWS_PER_BLK 128
#define WSTR 68

__device__ __forceinline__ void mma16816(
    float& c0, float& c1, float& c2, float& c3,
    uint32_t a0, uint32_t a1, uint32_t a2, uint32_t a3,
    uint32_t b0, uint32_t b1)
{
    asm volatile(
        "mma.sync.aligned.m16n8k16.row.col.f32.f16.f16.f32 "
        "{%0,%1,%2,%3}, {%4,%5,%6,%7}, {%8,%9}, {%0,%1,%2,%3};\n"
        : "+f"(c0), "+f"(c1), "+f"(c2), "+f"(c3)
        : "r"(a0), "r"(a1), "r"(a2), "r"(a3), "r"(b0), "r"(b1));
}

__global__ void __launch_bounds__(256, 2) dual_gemm_mma(
    const __half* __restrict__ A,     // [N][64] fp16
    const __half* __restrict__ Wh,
    const float* __restrict__ bias,
    __half* __restrict__ T,
    float*  __restrict__ H,
    int N)
{
    __shared__ __half sW[128 * WSTR];

    const int t = threadIdx.x;

#pragma unroll
    for (int i = 0; i < 8; i++) {
        int idx = t + 256 * i;
        int n = idx >> 4, kq = (idx & 15) * 4;
        uint2 v = *reinterpret_cast<const uint2*>(Wh + n * 64 + kq);
        *reinterpret_cast<uint2*>(sW + n * WSTR + kq) = v;
    }
    __syncthreads();

    const int warp = t >> 5, lane = t & 31;
    const int gid = lane >> 2, tig = lane & 3;
    const int rA = blockIdx.x * ROWS_PER_BLK + warp * 16 + gid;
    const int rB = rA + 8;
    const int rAl = (rA < N) ? rA : (N - 1);
    const int rBl = (rB < N) ? rB : (N - 1);
    const __half* Arow0 = A + (size_t)rAl * CDIM;
    const __half* Arow8 = A + (size_t)rBl * CDIM;

    float acc[16][4];
#pragma unroll
    for (int nt = 0; nt < 16; nt++)
#pragma unroll
        for (int j = 0; j < 4; j++) acc[nt][j] = 0.f;

#pragma unroll
    for (int ks = 0; ks < 4; ks++) {
        const int c = ks * 16 + tig * 2;
        uint32_t a0 = *reinterpret_cast<const uint32_t*>(Arow0 + c);
        uint32_t a1 = *reinterpret_cast<const uint32_t*>(Arow8 + c);
        uint32_t a2 = *reinterpret_cast<const uint32_t*>(Arow0 + c + 8);
        uint32_t a3 = *reinterpret_cast<const uint32_t*>(Arow8 + c + 8);

        const __half* wb = sW + ks * 16 + tig * 2 + gid * WSTR;
#pragma unroll
        for (int nt = 0; nt < 16; nt++) {
            const __half* wp = wb + nt * 8 * WSTR;
            uint32_t b0 = *reinterpret_cast<const uint32_t*>(wp);
            uint32_t b1 = *reinterpret_cast<const uint32_t*>(wp + 8);
            mma16816(acc[nt][0], acc[nt][1], acc[nt][2], acc[nt][3],
                     a0, a1, a2, a3, b0, b1);
        }
    }

#pragma unroll
    for (int nt = 0; nt < 8; nt++) {
        int col = nt * 8 + tig * 2;
        if (rA < N)
            *reinterpret_cast<uint32_t*>(T + (size_t)rA * CDIM + col) = f2toh2(acc[nt][0], acc[nt][1]);
        if (rB < N)
            *reinterpret_cast<uint32_t*>(T + (size_t)rB * CDIM + col) = f2toh2(acc[nt][2], acc[nt][3]);
    }
#pragma unroll
    for (int nt = 8; nt < 16; nt++) {
        int col = (nt - 8) * 8 + tig * 2;
        float2 bv = *reinterpret_cast<const float2*>(bias + col);
        if (rA < N) {
            float2 o; o.x = acc[nt][0] + bv.x; o.y = acc[nt][1] + bv.y;
            *reinterpret_cast<float2*>(H + (size_t)rA * CDIM + col) = o;
        }
        if (rB < N) {
            float2 o; o.x = acc[nt][2] + bv.x; o.y = acc[nt][3] + bv.y;
            *reinterpret_cast<float2*>(H + (size_t)rB * CDIM + col) = o;
        }
    }
}

// ---------------- host-side CSR build helper (4 kernels) ----------------
static void build_csr(const int* src, const int* dst, const float* attr, int E,
                      int* cnt, int* off, int* cur, int2* edges, int nNodes,
                      cudaStream_t s)
{
    const int n1 = nNodes + 1;
    const int nb = (n1 + 1023) / 1024;
    const int stateOff = (n1 + 3) & ~3;
    int* state = cnt + stateOff;
    zero_int<<<(stateOff + nb + 1023) / 1024, 256, 0, s>>>(cnt, stateOff + nb);
    hist_kernel<<<(E + 1023) / 1024, 256, 0, s>>>(dst, cnt, E);
    scan_lookback<<<nb, 256, 0, s>>>(cnt, state, off, cur, n1);
    permute_kernel<<<(E + 1023) / 1024, 256, 0, s>>>(src, dst, attr, cur, edges, E);
}

// ---------------- launch ----------------
extern "C" void kernel_launch(void* const* d_in, const int* in_sizes, int n_in,
                              void* d_out, int out_size)
{
    const float* x    = (const float*)d_in[0];
    const float* W1r  = (const float*)d_in[1];
    const float* W1n  = (const float*)d_in[2];
    const float* b1   = (const float*)d_in[3];
    const float* W2r  = (const float*)d_in[4];
    const float* W2n  = (const float*)d_in[5];
    const float* b2   = (const float*)d_in[6];
    const int*   psrc = (const int*)d_in[7];
    const int*   pdst = (const int*)d_in[8];
    const float* patt = (const float*)d_in[9];
    const int*   csrc = (const int*)d_in[10];
    const int*   cdst = (const int*)d_in[11];
    const float* catt = (const float*)d_in[12];
    const int*   usrc = (const int*)d_in[13];
    const int*   udst = (const int*)d_in[14];
    const float* uatt = (const float*)d_in[15];

    const int Ep = in_sizes[7];
    const int Ec = in_sizes[10];
    const int Eu = in_sizes[13];

    float* out = (float*)d_out;

    float* hb;
    __half *ab, *tb, *wh, *xh;
    cudaGetSymbolAddress((void**)&ab, g_a);
    cudaGetSymbolAddress((void**)&tb, g_t);
    cudaGetSymbolAddress((void**)&hb, g_h);
    cudaGetSymbolAddress((void**)&wh, g_wh);
    cudaGetSymbolAddress((void**)&xh, g_xh);
    __half* w1h = wh;
    __half* w2h = wh + 128 * 64;

    int *pcnt, *poff, *pcur, *ccnt, *coff, *ccur, *ucnt, *uoff, *ucur;
    int2 *pedg, *cedg, *uedg;
    cudaGetSymbolAddress((void**)&pcnt, g_pool_cnt);
    cudaGetSymbolAddress((void**)&poff, g_pool_off);
    cudaGetSymbolAddress((void**)&pcur, g_pool_cur);
    cudaGetSymbolAddress((void**)&pedg, g_pool_edges);
    cudaGetSymbolAddress((void**)&ccnt, g_conv_cnt);
    cudaGetSymbolAddress((void**)&coff, g_conv_off);
    cudaGetSymbolAddress((void**)&ccur, g_conv_cur);
    cudaGetSymbolAddress((void**)&cedg, g_conv_edges);
    cudaGetSymbolAddress((void**)&ucnt, g_unp_cnt);
    cudaGetSymbolAddress((void**)&uoff, g_unp_off);
    cudaGetSymbolAddress((void**)&ucur, g_unp_cur);
    cudaGetSymbolAddress((void**)&uedg, g_unp_edges);

    static cudaStream_t sB = nullptr, sC = nullptr;
    static cudaEvent_t ev0 = nullptr, evB = nullptr, evC = nullptr, evX = nullptr;
    if (sB == nullptr) {
        cudaStreamCreateWithFlags(&sB, cudaStreamNonBlocking);
        cudaStreamCreateWithFlags(&sC, cudaStreamNonBlocking);
        cudaEventCreateWithFlags(&ev0, cudaEventDisableTiming);
        cudaEventCreateWithFlags(&evB, cudaEventDisableTiming);
        cudaEventCreateWithFlags(&evC, cudaEventDisableTiming);
        cudaEventCreateWithFlags(&evX, cudaEventDisableTiming);
    }

    // weight conversion: one launch for both layers
    wconvert2<<<64, 256>>>(W1n, W1r, W2n, W2r, wh);

    // fork: x->fp16 + conv CSR on sB; unpool CSR on sC
    cudaEventRecord(ev0, 0);
    cudaStreamWaitEvent(sB, ev0, 0);
    cudaStreamWaitEvent(sC, ev0, 0);
    const int n8 = NFF * CDIM / 8;
    xconvert<<<(n8 + 255) / 256, 256, 0, sB>>>(x, xh, n8);
    cudaEventRecord(evX, sB);
    build_csr(csrc, cdst, catt, Ec, ccnt, coff, ccur, cedg, NCC, sB);
    cudaEventRecord(evB, sB);
    build_csr(usrc, udst, uatt, Eu, ucnt, uoff, ucur, uedg, NFF, sC);
    cudaEventRecord(evC, sC);

    // critical path
    build_csr(psrc, pdst, patt, Ep, pcnt, poff, pcur, pedg, NCC, 0);

    const int gthreadsC = NCC * 8;
    const int gthreadsF = NFF * 8;
    const int gemmBlocks = (NCC + ROWS_PER_BLK - 1) / ROWS_PER_BLK;

    // pool: a = gather(xh)  [fp16 -> fp16]
    cudaStreamWaitEvent(0, evX, 0);
    gather_h<false, true, false><<<(gthreadsC + 255) / 256, 256>>>(
        xh, pedg, poff, nullptr, nullptr, ab, NCC);

    // layer 1: (T, H) = gemm(a); a = H + gather(T)
    dual_gemm_mma<<<gemmBlocks, 256>>>(ab, w1h, b1, tb, hb, NCC);
    cudaStreamWaitEvent(0, evB, 0);
    gather_h<true, true, false><<<(gthreadsC + 255) / 256, 256>>>(
        tb, cedg, coff, hb, nullptr, ab, NCC);

    // layer 2: (T, H) = gemm(a); a = H + gather(T)
    dual_gemm_mma<<<gemmBlocks, 256>>>(ab, w2h, b2, tb, hb, NCC);
    gather_h<true, true, false><<<(gthreadsC + 255) / 256, 256>>>(
        tb, cedg, coff, hb, nullptr, ab, NCC);

    // unpool: out = gather(a)  [fp16 -> fp32, streaming stores]
    cudaStreamWaitEvent(0, evC, 0);
    gather_h<false, false, true><<<(gthreadsF + 255) / 256, 256>>>(
        ab, uedg, uoff, nullptr, out, nullptr, NFF);
}